// round 6
// baseline (speedup 1.0000x reference)
#include <cuda_runtime.h>
#include <math.h>

// Problem dims
#define TT 1024
#define BB 128
#define VV 512
#define HH 2048
#define OO 512

constexpr int KB      = 16;               // K depth per SMEM stage
constexpr int NTH     = 256;              // threads per CTA
constexpr int KSPLIT  = 8;                // split-K factor in the scan
constexpr int NTILES  = HH / 128;         // 16 N-tiles of 128 cols
constexpr int KCH     = HH / KSPLIT;      // 256 K per split

constexpr int    BH  = BB * HH;                 // 262144
constexpr size_t TBH = (size_t)TT * BH;
constexpr size_t TBO = (size_t)TT * BB * OO;

// -------- device scratch (no cudaMalloc allowed) --------
__device__ float g_P[VV * HH];                    // P = emb @ Wi^T + bi (4 MB)
__device__ float g_hall[TBH];                     // all hidden states  [T][B][H]
__device__ float g_part[KSPLIT * (size_t)BH];     // split-K partials   [8][B][H]
__device__ int   g_ctr_tile[TT][NTILES];          // per-step per-N-tile arrivals
__device__ int   g_ctr_step[TT];                  // per-step global arrivals

// -------- packed f32x2 helpers (FFMA2 is PTX-only on sm_103a) --------
typedef unsigned long long ull;

__device__ __forceinline__ void ffma2(ull& d, ull a, ull b) {
    asm("fma.rn.f32x2 %0, %1, %2, %3;" : "=l"(d) : "l"(a), "l"(b), "l"(d));
}
__device__ __forceinline__ void unpack2(float& lo, float& hi, ull v) {
    asm("mov.b64 {%0,%1}, %2;" : "=f"(lo), "=f"(hi) : "l"(v));
}
__device__ __forceinline__ ull dup2(float v) {
    ull r; asm("mov.b64 %0, {%1,%1};" : "=l"(r) : "f"(v)); return r;
}

// ============================================================================
// Shared 128x128 CTA-tile fp32 GEMM core (NT layout: C[m,n] = sum_k A[m,k]B[n,k])
//   256 threads, per-thread tile 8 M-rows (4 f32x2 pairs) x 8 N-cols.
//   B duplicated into f32x2 in REGISTERS (mov.b64 {b,b}) -> 1 B/MAC SMEM traffic.
//   Bs columns skewed by 4 floats per 32-col group -> conflict-free LDS.128.
// ============================================================================
struct SmemT {
    float As[2][KB][132];   // [k][m], stride 132 (16B-aligned rows, de-conflicted STS)
    float Bs[2][KB][140];   // [k][n_skewed]
};

__device__ __forceinline__ int skew(int n) { return n + ((n >> 5) << 2); }

__device__ __forceinline__ void gemm_tile(SmemT& s,
    const float* __restrict__ Ag, int lda,
    const float* __restrict__ Bg, int ldb,
    int nk, ull (&acc)[4][8])
{
    const int tid = threadIdx.x;
    const int am  = tid >> 2;          // load row 0..63 (and +64)
    const int ak  = (tid & 3) * 4;     // load k offset (float4)
    const int tm  = (tid >> 4) * 8;    // thread M base (8 rows)
    const int tn  = (tid & 15) * 8;    // thread N base (8 cols)
    const int ptn = skew(tn);
    const int pb0 = skew(am);
    const int pb1 = skew(am + 64);

    const float* Arow0 = Ag + (size_t)am        * lda + ak;
    const float* Arow1 = Ag + (size_t)(am + 64) * lda + ak;
    const float* Brow0 = Bg + (size_t)am        * ldb + ak;
    const float* Brow1 = Bg + (size_t)(am + 64) * ldb + ak;

    float4 ra0, ra1, rb0, rb1;
    auto ldg = [&](int kt) {
        const int kk = kt * KB;
        ra0 = *(const float4*)(Arow0 + kk);
        ra1 = *(const float4*)(Arow1 + kk);
        rb0 = *(const float4*)(Brow0 + kk);
        rb1 = *(const float4*)(Brow1 + kk);
    };
    auto sts = [&](int buf) {
        s.As[buf][ak + 0][am]      = ra0.x; s.As[buf][ak + 1][am]      = ra0.y;
        s.As[buf][ak + 2][am]      = ra0.z; s.As[buf][ak + 3][am]      = ra0.w;
        s.As[buf][ak + 0][am + 64] = ra1.x; s.As[buf][ak + 1][am + 64] = ra1.y;
        s.As[buf][ak + 2][am + 64] = ra1.z; s.As[buf][ak + 3][am + 64] = ra1.w;
        s.Bs[buf][ak + 0][pb0] = rb0.x; s.Bs[buf][ak + 1][pb0] = rb0.y;
        s.Bs[buf][ak + 2][pb0] = rb0.z; s.Bs[buf][ak + 3][pb0] = rb0.w;
        s.Bs[buf][ak + 0][pb1] = rb1.x; s.Bs[buf][ak + 1][pb1] = rb1.y;
        s.Bs[buf][ak + 2][pb1] = rb1.z; s.Bs[buf][ak + 3][pb1] = rb1.w;
    };

    ldg(0); sts(0);
    __syncthreads();

    for (int kt = 0; kt < nk; ++kt) {
        const int cur = kt & 1;
        if (kt + 1 < nk) ldg(kt + 1);
        #pragma unroll
        for (int k = 0; k < KB; ++k) {
            ulonglong2 a01 = *(const ulonglong2*)&s.As[cur][k][tm];      // pairs (m0,m1)(m2,m3)
            ulonglong2 a23 = *(const ulonglong2*)&s.As[cur][k][tm + 4];  // pairs (m4,m5)(m6,m7)
            float4 b0 = *(const float4*)&s.Bs[cur][k][ptn];
            float4 b1 = *(const float4*)&s.Bs[cur][k][ptn + 4];
            ull d0 = dup2(b0.x), d1 = dup2(b0.y), d2 = dup2(b0.z), d3 = dup2(b0.w);
            ull d4 = dup2(b1.x), d5 = dup2(b1.y), d6 = dup2(b1.z), d7 = dup2(b1.w);
            ffma2(acc[0][0], a01.x, d0); ffma2(acc[0][1], a01.x, d1);
            ffma2(acc[0][2], a01.x, d2); ffma2(acc[0][3], a01.x, d3);
            ffma2(acc[0][4], a01.x, d4); ffma2(acc[0][5], a01.x, d5);
            ffma2(acc[0][6], a01.x, d6); ffma2(acc[0][7], a01.x, d7);
            ffma2(acc[1][0], a01.y, d0); ffma2(acc[1][1], a01.y, d1);
            ffma2(acc[1][2], a01.y, d2); ffma2(acc[1][3], a01.y, d3);
            ffma2(acc[1][4], a01.y, d4); ffma2(acc[1][5], a01.y, d5);
            ffma2(acc[1][6], a01.y, d6); ffma2(acc[1][7], a01.y, d7);
            ffma2(acc[2][0], a23.x, d0); ffma2(acc[2][1], a23.x, d1);
            ffma2(acc[2][2], a23.x, d2); ffma2(acc[2][3], a23.x, d3);
            ffma2(acc[2][4], a23.x, d4); ffma2(acc[2][5], a23.x, d5);
            ffma2(acc[2][6], a23.x, d6); ffma2(acc[2][7], a23.x, d7);
            ffma2(acc[3][0], a23.y, d0); ffma2(acc[3][1], a23.y, d1);
            ffma2(acc[3][2], a23.y, d2); ffma2(acc[3][3], a23.y, d3);
            ffma2(acc[3][4], a23.y, d4); ffma2(acc[3][5], a23.y, d5);
            ffma2(acc[3][6], a23.y, d6); ffma2(acc[3][7], a23.y, d7);
        }
        if (kt + 1 < nk) sts(cur ^ 1);
        __syncthreads();
    }
}

// ============================================================================
// Generic 128x128-tile GEMM kernel (phases 1 and 3): C = A @ B^T + bias
// ============================================================================
__global__ void __launch_bounds__(NTH, 1)
gemm128(const float* __restrict__ A, int lda,
        const float* __restrict__ B, int ldb,
        float* __restrict__ C, int ldc,
        const float* __restrict__ bias, int K)
{
    __shared__ SmemT s;
    const int tid   = threadIdx.x;
    const int nbase = blockIdx.x * 128;
    const int mbase = blockIdx.y * 128;

    ull acc[4][8];
    #pragma unroll
    for (int p = 0; p < 4; ++p)
        #pragma unroll
        for (int n = 0; n < 8; ++n) acc[p][n] = 0ull;

    gemm_tile(s, A + (size_t)mbase * lda, lda, B + (size_t)nbase * ldb, ldb,
              K / KB, acc);

    const int tm = (tid >> 4) * 8;
    const int tn = (tid & 15) * 8;
    float bv[8];
    #pragma unroll
    for (int n = 0; n < 8; ++n) bv[n] = bias[nbase + tn + n];

    #pragma unroll
    for (int p = 0; p < 4; ++p) {
        float lo[8], hi[8];
        #pragma unroll
        for (int n = 0; n < 8; ++n) {
            unpack2(lo[n], hi[n], acc[p][n]);
            lo[n] += bv[n]; hi[n] += bv[n];
        }
        const int r0 = mbase + tm + 2 * p;
        float* c0 = C + (size_t)r0 * ldc + nbase + tn;
        float* c1 = c0 + ldc;
        *(float4*)(c0)     = make_float4(lo[0], lo[1], lo[2], lo[3]);
        *(float4*)(c0 + 4) = make_float4(lo[4], lo[5], lo[6], lo[7]);
        *(float4*)(c1)     = make_float4(hi[0], hi[1], hi[2], hi[3]);
        *(float4*)(c1 + 4) = make_float4(hi[4], hi[5], hi[6], hi[7]);
    }
}

// ============================================================================
// Persistent scan kernel: all 1024 steps in ONE launch.
//   grid = (16 N-tiles, 8 K-splits) = 128 CTAs, single wave (<=148 SMs).
//   Per step: each CTA computes its split-K partial of h_{t-1} @ Wh^T,
//   per-N-tile barrier, distributed reduce+tanh into g_hall[t], global barrier.
// ============================================================================
__global__ void __launch_bounds__(NTH, 1)
scan_kernel(const int* __restrict__ x,
            const float* __restrict__ Wh,
            const float* __restrict__ bh)
{
    __shared__ SmemT s;
    const int tid   = threadIdx.x;
    const int j     = blockIdx.x;          // N-tile 0..15
    const int z     = blockIdx.y;          // K-split 0..7
    const int nbase = j * 128;
    const int k0    = z * KCH;

    // reduce/init slice: this CTA owns cols [nbase + z*16, +16), all 128 rows.
    const int rrow  = tid >> 1;                         // 0..127
    const int cbase = nbase + z * 16 + (tid & 1) * 8;   // 8 cols per thread

    const int tm = (tid >> 4) * 8;
    const int tn = (tid & 15) * 8;

    // ---- t = 0: h_0 = tanh(P[x_0] + bh) ----
    {
        const float* Pr = g_P + (size_t)x[rrow] * HH + cbase;
        float4 p0 = *(const float4*)(Pr);
        float4 p1 = *(const float4*)(Pr + 4);
        float4 h0 = *(const float4*)(bh + cbase);
        float4 h1 = *(const float4*)(bh + cbase + 4);
        float* dst = g_hall + (size_t)rrow * HH + cbase;
        *(float4*)(dst)     = make_float4(tanhf(p0.x + h0.x), tanhf(p0.y + h0.y),
                                          tanhf(p0.z + h0.z), tanhf(p0.w + h0.w));
        *(float4*)(dst + 4) = make_float4(tanhf(p1.x + h1.x), tanhf(p1.y + h1.y),
                                          tanhf(p1.z + h1.z), tanhf(p1.w + h1.w));
        __threadfence();
        __syncthreads();
        if (tid == 0) {
            atomicAdd(&g_ctr_step[0], 1);
            while (*(volatile int*)&g_ctr_step[0] < 128) __nanosleep(40);
            __threadfence();
        }
        __syncthreads();
    }

    // ---- t = 1 .. T-1 ----
    for (int t = 1; t < TT; ++t) {
        ull acc[4][8];
        #pragma unroll
        for (int p = 0; p < 4; ++p)
            #pragma unroll
            for (int n = 0; n < 8; ++n) acc[p][n] = 0ull;

        gemm_tile(s,
                  g_hall + (size_t)(t - 1) * BH + k0, HH,
                  Wh + (size_t)nbase * HH + k0, HH,
                  KCH / KB, acc);

        // store split-K partial plane z, cols [nbase+tn, +8), rows tm..tm+7
        float* Cz = g_part + (size_t)z * BH;
        #pragma unroll
        for (int p = 0; p < 4; ++p) {
            float lo[8], hi[8];
            #pragma unroll
            for (int n = 0; n < 8; ++n) unpack2(lo[n], hi[n], acc[p][n]);
            const int r0 = tm + 2 * p;
            float* c0 = Cz + (size_t)r0 * HH + nbase + tn;
            float* c1 = c0 + HH;
            *(float4*)(c0)     = make_float4(lo[0], lo[1], lo[2], lo[3]);
            *(float4*)(c0 + 4) = make_float4(lo[4], lo[5], lo[6], lo[7]);
            *(float4*)(c1)     = make_float4(hi[0], hi[1], hi[2], hi[3]);
            *(float4*)(c1 + 4) = make_float4(hi[4], hi[5], hi[6], hi[7]);
        }
        __threadfence();
        __syncthreads();

        // per-N-tile barrier: wait for all 8 split-K partials of tile j
        if (tid == 0) {
            atomicAdd(&g_ctr_tile[t][j], 1);
            while (*(volatile int*)&g_ctr_tile[t][j] < KSPLIT) { }
            __threadfence();
        }
        __syncthreads();

        // distributed reduce + tanh over this CTA's 128x16 slice
        {
            const float* Pr = g_P + (size_t)x[(size_t)t * BB + rrow] * HH + cbase;
            float4 p0 = *(const float4*)(Pr);
            float4 p1 = *(const float4*)(Pr + 4);
            float4 h0 = *(const float4*)(bh + cbase);
            float4 h1 = *(const float4*)(bh + cbase + 4);
            float4 v0 = make_float4(p0.x + h0.x, p0.y + h0.y, p0.z + h0.z, p0.w + h0.w);
            float4 v1 = make_float4(p1.x + h1.x, p1.y + h1.y, p1.z + h1.z, p1.w + h1.w);
            const size_t off = (size_t)rrow * HH + cbase;
            #pragma unroll
            for (int z2 = 0; z2 < KSPLIT; ++z2) {
                float4 u0 = __ldcg((const float4*)(g_part + (size_t)z2 * BH + off));
                float4 u1 = __ldcg((const float4*)(g_part + (size_t)z2 * BH + off + 4));
                v0.x += u0.x; v0.y += u0.y; v0.z += u0.z; v0.w += u0.w;
                v1.x += u1.x; v1.y += u1.y; v1.z += u1.z; v1.w += u1.w;
            }
            float* dst = g_hall + (size_t)t * BH + off;
            *(float4*)(dst)     = make_float4(tanhf(v0.x), tanhf(v0.y),
                                              tanhf(v0.z), tanhf(v0.w));
            *(float4*)(dst + 4) = make_float4(tanhf(v1.x), tanhf(v1.y),
                                              tanhf(v1.z), tanhf(v1.w));
        }
        __threadfence();
        __syncthreads();

        // global barrier: h_t fully written before anyone starts step t+1
        if (tid == 0) {
            atomicAdd(&g_ctr_step[t], 1);
            while (*(volatile int*)&g_ctr_step[t] < 128) __nanosleep(40);
            __threadfence();
        }
        __syncthreads();
    }
}

// Reset barrier counters for the next kernel_launch invocation / graph replay.
__global__ void reset_ctr_kernel()
{
    const int i = blockIdx.x * blockDim.x + threadIdx.x;
    if (i < TT * NTILES) ((int*)g_ctr_tile)[i] = 0;
    if (i < TT) g_ctr_step[i] = 0;
}

__global__ void copy_h_kernel(float* __restrict__ dst)
{
    const int idx = blockIdx.x * blockDim.x + threadIdx.x;   // over B*H
    dst[idx] = g_hall[(size_t)(TT - 1) * BH + idx];
}

extern "C" void kernel_launch(void* const* d_in, const int* in_sizes, int n_in,
                              void* d_out, int out_size)
{
    (void)in_sizes; (void)n_in;
    const int*   x   = (const int*)  d_in[0];
    const float* emb = (const float*)d_in[1];
    const float* Wi  = (const float*)d_in[2];
    const float* bi  = (const float*)d_in[3];
    const float* Wh  = (const float*)d_in[4];
    const float* bh  = (const float*)d_in[5];
    const float* Wo  = (const float*)d_in[6];
    const float* bo  = (const float*)d_in[7];
    float* out = (float*)d_out;

    float* g_P_ptr    = nullptr;
    float* g_hall_ptr = nullptr;
    cudaGetSymbolAddress((void**)&g_P_ptr,    g_P);
    cudaGetSymbolAddress((void**)&g_hall_ptr, g_hall);

    // Phase 1: P = emb @ Wi^T + bi   [512 x 2048], K=512
    gemm128<<<dim3(HH / 128, VV / 128), NTH>>>(emb, VV, Wi, VV,
                                               g_P_ptr, HH, bi, VV);

    // Phase 2: persistent scan (all 1024 steps, one launch)
    scan_kernel<<<dim3(NTILES, KSPLIT), NTH>>>(x, Wh, bh);

    // Reset spin counters for the next invocation (stream-ordered after scan)
    reset_ctr_kernel<<<(TT * NTILES + NTH - 1) / NTH, NTH>>>();

    // Phase 3: out = h_all @ Wo^T + bo   [131072 x 512], K=2048
    gemm128<<<dim3(OO / 128, (TT * BB) / 128), NTH>>>(g_hall_ptr, HH, Wo, HH,
                                                      out, OO, bo, HH);

    // Second output: final hidden state h_{T-1}  [B, H]
    if ((long long)out_size >= (long long)(TBO + (size_t)BH))
        copy_h_kernel<<<BH / NTH, NTH>>>(out + TBO);
}

// round 8
// speedup vs baseline: 1.2002x; 1.2002x over previous
#include <cuda_runtime.h>
#include <cuda_bf16.h>
#include <math.h>
#include <cstdint>

// Problem dims
#define TT 1024
#define BB 128
#define VV 512
#define HH 2048
#define OO 512

constexpr int NTH    = 256;
constexpr int KSPLIT = 8;
constexpr int NTILES = HH / 128;     // 16
constexpr int KCH    = HH / KSPLIT;  // 256
constexpr int KSTAGE = 32;           // fp32 K-depth per SMEM stage

constexpr int    BH  = BB * HH;
constexpr size_t TBH = (size_t)TT * BH;
constexpr size_t TBO = (size_t)TT * BB * OO;

// -------- device scratch --------
__device__ float g_P[VV * HH];
__device__ float g_hall[TBH];
__device__ float g_part[KSPLIT * (size_t)BH];
__device__ int   g_ctr_tile[TT][NTILES];
__device__ int   g_ctr_step[TT];

// ============================================================================
// bf16x2 split + mma.sync helpers (legacy tensor path; no tcgen05 on this
// toolchain — it builds PTX for compute_103 without the 'a' feature set)
// ============================================================================
__device__ __forceinline__ void split2(float v0, float v1,
                                       uint32_t& whi, uint32_t& wlo) {
    __nv_bfloat16 h0 = __float2bfloat16_rn(v0);
    __nv_bfloat16 h1 = __float2bfloat16_rn(v1);
    __nv_bfloat16 l0 = __float2bfloat16_rn(v0 - __bfloat162float(h0));
    __nv_bfloat16 l1 = __float2bfloat16_rn(v1 - __bfloat162float(h1));
    whi = ((uint32_t)__bfloat16_as_ushort(h1) << 16) | __bfloat16_as_ushort(h0);
    wlo = ((uint32_t)__bfloat16_as_ushort(l1) << 16) | __bfloat16_as_ushort(l0);
}

__device__ __forceinline__ void mma_bf16(float* d, const uint32_t* a,
                                         const uint32_t* b) {
    asm volatile(
        "mma.sync.aligned.m16n8k16.row.col.f32.bf16.bf16.f32 "
        "{%0,%1,%2,%3}, {%4,%5,%6,%7}, {%8,%9}, {%0,%1,%2,%3};"
        : "+f"(d[0]), "+f"(d[1]), "+f"(d[2]), "+f"(d[3])
        : "r"(a[0]), "r"(a[1]), "r"(a[2]), "r"(a[3]), "r"(b[0]), "r"(b[1]));
}

// SMEM tiles: 128 rows x 16 b32-words (32 bf16) per tile, padded to 18 words.
constexpr int TW      = 18;                 // words per row (16 + 2 pad)
constexpr int TILE_W  = 128 * TW;           // 2304 words per tile
constexpr int SMEM_TC = 2 * 4 * TILE_W * 4; // 2 bufs x {Ahi,Alo,Bhi,Blo} = 73728 B

__device__ __forceinline__ uint32_t* tile_ptr(uint32_t* sm, int buf, int which) {
    return sm + (buf * 4 + which) * TILE_W;
}

// One K=32 stage of bf16x2 x3-product MMAs for this warp's 32x64 output tile.
__device__ __forceinline__ void mma_stage(
    const uint32_t* __restrict__ Ahi, const uint32_t* __restrict__ Alo,
    const uint32_t* __restrict__ Bhi, const uint32_t* __restrict__ Blo,
    int wrow, int wcol, int lane, float (&d)[2][8][4])
{
    #pragma unroll
    for (int kk = 0; kk < 2; ++kk) {                 // two k16 steps
        const int kw = kk * 8 + (lane & 3);
        uint32_t ah[2][4], al[2][4];
        #pragma unroll
        for (int m = 0; m < 2; ++m) {
            const int r = (wrow + m * 16 + (lane >> 2)) * TW;
            ah[m][0] = Ahi[r + kw];          ah[m][1] = Ahi[r + 8 * TW + kw];
            ah[m][2] = Ahi[r + kw + 4];      ah[m][3] = Ahi[r + 8 * TW + kw + 4];
            al[m][0] = Alo[r + kw];          al[m][1] = Alo[r + 8 * TW + kw];
            al[m][2] = Alo[r + kw + 4];      al[m][3] = Alo[r + 8 * TW + kw + 4];
        }
        #pragma unroll
        for (int n = 0; n < 8; ++n) {
            const int rb = (wcol + n * 8 + (lane >> 2)) * TW;
            uint32_t bh[2] = { Bhi[rb + kw], Bhi[rb + kw + 4] };
            uint32_t bl[2] = { Blo[rb + kw], Blo[rb + kw + 4] };
            #pragma unroll
            for (int m = 0; m < 2; ++m) {
                mma_bf16(d[m][n], ah[m], bh);    // hi*hi
                mma_bf16(d[m][n], ah[m], bl);    // hi*lo
                mma_bf16(d[m][n], al[m], bh);    // lo*hi
            }
        }
    }
}

// Producer: each thread covers row = tid>>1, 16 cols at (tid&1)*16.
struct StageRegs { float4 ra[4], rb[4]; };

__device__ __forceinline__ void stage_ldg(StageRegs& g,
    const float* __restrict__ Asrc, const float* __restrict__ Bsrc,
    int prow, int pcol, int s)
{
    const float* ap = Asrc + (size_t)prow * HH + pcol + s * KSTAGE;
    const float* bp = Bsrc + (size_t)prow * HH + pcol + s * KSTAGE;
    #pragma unroll
    for (int i = 0; i < 4; ++i) {
        g.ra[i] = *(const float4*)(ap + 4 * i);
        g.rb[i] = *(const float4*)(bp + 4 * i);
    }
}

__device__ __forceinline__ void stage_sts(uint32_t* sm, int buf,
    const StageRegs& g, int prow, int pcol2 /* (tid&1)*8 words */)
{
    uint32_t* ah = tile_ptr(sm, buf, 0) + prow * TW + pcol2;
    uint32_t* al = tile_ptr(sm, buf, 1) + prow * TW + pcol2;
    uint32_t* bh = tile_ptr(sm, buf, 2) + prow * TW + pcol2;
    uint32_t* bl = tile_ptr(sm, buf, 3) + prow * TW + pcol2;
    #pragma unroll
    for (int i = 0; i < 4; ++i) {
        uint32_t h0, l0, h1, l1;
        split2(g.ra[i].x, g.ra[i].y, h0, l0);
        split2(g.ra[i].z, g.ra[i].w, h1, l1);
        *(uint2*)(ah + 2 * i) = make_uint2(h0, h1);
        *(uint2*)(al + 2 * i) = make_uint2(l0, l1);
        split2(g.rb[i].x, g.rb[i].y, h0, l0);
        split2(g.rb[i].z, g.rb[i].w, h1, l1);
        *(uint2*)(bh + 2 * i) = make_uint2(h0, h1);
        *(uint2*)(bl + 2 * i) = make_uint2(l0, l1);
    }
}

// ============================================================================
// Persistent scan kernel (mma.sync bf16x2), grid (16 N-tiles, 8 K-splits)
// ============================================================================
__global__ void __launch_bounds__(NTH, 1)
scan_mma(const int* __restrict__ x,
         const float* __restrict__ Wh,
         const float* __restrict__ bh)
{
    extern __shared__ uint32_t sm[];

    const int tid  = threadIdx.x;
    const int wid  = tid >> 5;
    const int lane = tid & 31;
    const int j    = blockIdx.x;
    const int z    = blockIdx.y;
    const int nbase = j * 128;
    const int k0    = z * KCH;

    const int wrow = (wid & 3) * 32;    // warp's 32 output rows
    const int wcol = (wid >> 2) * 64;   // warp's 64 output cols
    const int prow = tid >> 1;          // producer row
    const int pcol = (tid & 1) * 16;    // producer col (floats)
    const int pcw  = (tid & 1) * 8;     // producer col (b32 words)

    // reduce/init slice mapping (verified R6)
    const int rrow  = tid >> 1;
    const int cbase = nbase + z * 16 + (tid & 1) * 8;

    // ---- t = 0: h_0 = tanh(P[x_0] + bh) ----
    {
        const float* Pr = g_P + (size_t)x[rrow] * HH + cbase;
        float4 p0 = *(const float4*)(Pr);
        float4 p1 = *(const float4*)(Pr + 4);
        float4 b0 = *(const float4*)(bh + cbase);
        float4 b1 = *(const float4*)(bh + cbase + 4);
        float* dst = g_hall + (size_t)rrow * HH + cbase;
        *(float4*)(dst)     = make_float4(tanhf(p0.x + b0.x), tanhf(p0.y + b0.y),
                                          tanhf(p0.z + b0.z), tanhf(p0.w + b0.w));
        *(float4*)(dst + 4) = make_float4(tanhf(p1.x + b1.x), tanhf(p1.y + b1.y),
                                          tanhf(p1.z + b1.z), tanhf(p1.w + b1.w));
        __threadfence();
        __syncthreads();
        if (tid == 0) {
            atomicAdd(&g_ctr_step[0], 1);
            while (*(volatile int*)&g_ctr_step[0] < 128) __nanosleep(40);
            __threadfence();
        }
        __syncthreads();
    }

    for (int t = 1; t < TT; ++t) {
        const float* Asrc = g_hall + (size_t)(t - 1) * BH + k0;
        const float* Bsrc = Wh + (size_t)nbase * HH + k0;

        float d[2][8][4];
        #pragma unroll
        for (int m = 0; m < 2; ++m)
            #pragma unroll
            for (int n = 0; n < 8; ++n)
                #pragma unroll
                for (int q = 0; q < 4; ++q) d[m][n][q] = 0.0f;

        StageRegs g;
        stage_ldg(g, Asrc, Bsrc, prow, pcol, 0);
        stage_sts(sm, 0, g, prow, pcw);
        __syncthreads();

        constexpr int NS = KCH / KSTAGE;   // 8 stages
        #pragma unroll 1
        for (int s = 0; s < NS; ++s) {
            const int cur = s & 1;
            if (s + 1 < NS) stage_ldg(g, Asrc, Bsrc, prow, pcol, s + 1);
            mma_stage(tile_ptr(sm, cur, 0), tile_ptr(sm, cur, 1),
                      tile_ptr(sm, cur, 2), tile_ptr(sm, cur, 3),
                      wrow, wcol, lane, d);
            if (s + 1 < NS) stage_sts(sm, cur ^ 1, g, prow, pcw);
            __syncthreads();
        }

        // store split-K partial plane z
        {
            float* dst = g_part + (size_t)z * BH;
            #pragma unroll
            for (int m = 0; m < 2; ++m)
                #pragma unroll
                for (int n = 0; n < 8; ++n) {
                    const int r0 = wrow + m * 16 + (lane >> 2);
                    const int c0 = nbase + wcol + n * 8 + (lane & 3) * 2;
                    *(float2*)(dst + (size_t)r0 * HH + c0) =
                        make_float2(d[m][n][0], d[m][n][1]);
                    *(float2*)(dst + (size_t)(r0 + 8) * HH + c0) =
                        make_float2(d[m][n][2], d[m][n][3]);
                }
        }
        __threadfence();
        __syncthreads();

        // per-N-tile barrier: all 8 split-K planes of tile j present
        if (tid == 0) {
            atomicAdd(&g_ctr_tile[t][j], 1);
            while (*(volatile int*)&g_ctr_tile[t][j] < KSPLIT) { }
            __threadfence();
        }
        __syncthreads();

        // distributed reduce + tanh over this CTA's 128x16 slice
        {
            const float* Pr = g_P + (size_t)x[(size_t)t * BB + rrow] * HH + cbase;
            float4 p0 = *(const float4*)(Pr);
            float4 p1 = *(const float4*)(Pr + 4);
            float4 b0 = *(const float4*)(bh + cbase);
            float4 b1 = *(const float4*)(bh + cbase + 4);
            float4 v0 = make_float4(p0.x + b0.x, p0.y + b0.y, p0.z + b0.z, p0.w + b0.w);
            float4 v1 = make_float4(p1.x + b1.x, p1.y + b1.y, p1.z + b1.z, p1.w + b1.w);
            const size_t off = (size_t)rrow * HH + cbase;
            #pragma unroll
            for (int z2 = 0; z2 < KSPLIT; ++z2) {
                float4 u0 = __ldcg((const float4*)(g_part + (size_t)z2 * BH + off));
                float4 u1 = __ldcg((const float4*)(g_part + (size_t)z2 * BH + off + 4));
                v0.x += u0.x; v0.y += u0.y; v0.z += u0.z; v0.w += u0.w;
                v1.x += u1.x; v1.y += u1.y; v1.z += u1.z; v1.w += u1.w;
            }
            float* dst = g_hall + (size_t)t * BH + off;
            *(float4*)(dst)     = make_float4(tanhf(v0.x), tanhf(v0.y),
                                              tanhf(v0.z), tanhf(v0.w));
            *(float4*)(dst + 4) = make_float4(tanhf(v1.x), tanhf(v1.y),
                                              tanhf(v1.z), tanhf(v1.w));
        }
        __threadfence();
        __syncthreads();

        // global barrier: h_t complete before anyone loads it at t+1
        if (tid == 0) {
            atomicAdd(&g_ctr_step[t], 1);
            while (*(volatile int*)&g_ctr_step[t] < 128) __nanosleep(40);
            __threadfence();
        }
        __syncthreads();
    }
}

// ============================================================================
// Phase-3 GEMM (mma.sync bf16x2): out = h_all @ Wo^T + bo
//   grid (4 N-tiles, 1024 M-tiles), K = 2048 -> 64 stages
// ============================================================================
__global__ void __launch_bounds__(NTH, 1)
gemm_out_mma(const float* __restrict__ Wo,
             const float* __restrict__ bo,
             float* __restrict__ out)
{
    extern __shared__ uint32_t sm[];

    const int tid  = threadIdx.x;
    const int wid  = tid >> 5;
    const int lane = tid & 31;
    const int nbase = blockIdx.x * 128;
    const size_t mbase = (size_t)blockIdx.y * 128;

    const int wrow = (wid & 3) * 32;
    const int wcol = (wid >> 2) * 64;
    const int prow = tid >> 1;
    const int pcol = (tid & 1) * 16;
    const int pcw  = (tid & 1) * 8;

    const float* Asrc = g_hall + mbase * HH;
    const float* Bsrc = Wo + (size_t)nbase * HH;

    float d[2][8][4];
    #pragma unroll
    for (int m = 0; m < 2; ++m)
        #pragma unroll
        for (int n = 0; n < 8; ++n)
            #pragma unroll
            for (int q = 0; q < 4; ++q) d[m][n][q] = 0.0f;

    StageRegs g;
    stage_ldg(g, Asrc, Bsrc, prow, pcol, 0);
    stage_sts(sm, 0, g, prow, pcw);
    __syncthreads();

    constexpr int NS = HH / KSTAGE;   // 64 stages
    #pragma unroll 1
    for (int s = 0; s < NS; ++s) {
        const int cur = s & 1;
        if (s + 1 < NS) stage_ldg(g, Asrc, Bsrc, prow, pcol, s + 1);
        mma_stage(tile_ptr(sm, cur, 0), tile_ptr(sm, cur, 1),
                  tile_ptr(sm, cur, 2), tile_ptr(sm, cur, 3),
                  wrow, wcol, lane, d);
        if (s + 1 < NS) stage_sts(sm, cur ^ 1, g, prow, pcw);
        __syncthreads();
    }

    // epilogue: + bias, store
    #pragma unroll
    for (int m = 0; m < 2; ++m)
        #pragma unroll
        for (int n = 0; n < 8; ++n) {
            const int r0 = wrow + m * 16 + (lane >> 2);
            const int c0 = nbase + wcol + n * 8 + (lane & 3) * 2;
            const float2 bv = *(const float2*)(bo + c0);
            *(float2*)(out + (mbase + r0) * OO + c0) =
                make_float2(d[m][n][0] + bv.x, d[m][n][1] + bv.y);
            *(float2*)(out + (mbase + r0 + 8) * OO + c0) =
                make_float2(d[m][n][2] + bv.x, d[m][n][3] + bv.y);
        }
}

// ============================================================================
// Phase-1 fp32 FFMA2 GEMM (exact; verified R6 code)
// ============================================================================
typedef unsigned long long ull;
__device__ __forceinline__ void ffma2(ull& d, ull a, ull b) {
    asm("fma.rn.f32x2 %0, %1, %2, %3;" : "=l"(d) : "l"(a), "l"(b), "l"(d));
}
__device__ __forceinline__ void unpack2(float& lo, float& hi, ull v) {
    asm("mov.b64 {%0,%1}, %2;" : "=f"(lo), "=f"(hi) : "l"(v));
}
__device__ __forceinline__ ull dup2(float v) {
    ull r; asm("mov.b64 %0, {%1,%1};" : "=l"(r) : "f"(v)); return r;
}
constexpr int KB = 16;
struct SmemT {
    float As[2][KB][132];
    float Bs[2][KB][140];
};
__device__ __forceinline__ int skew(int n) { return n + ((n >> 5) << 2); }

__device__ __forceinline__ void gemm_tile(SmemT& s,
    const float* __restrict__ Ag, int lda,
    const float* __restrict__ Bg, int ldb,
    int nk, ull (&acc)[4][8])
{
    const int tid = threadIdx.x;
    const int am  = tid >> 2;
    const int ak  = (tid & 3) * 4;
    const int tm  = (tid >> 4) * 8;
    const int tn  = (tid & 15) * 8;
    const int ptn = skew(tn);
    const int pb0 = skew(am);
    const int pb1 = skew(am + 64);

    const float* Arow0 = Ag + (size_t)am        * lda + ak;
    const float* Arow1 = Ag + (size_t)(am + 64) * lda + ak;
    const float* Brow0 = Bg + (size_t)am        * ldb + ak;
    const float* Brow1 = Bg + (size_t)(am + 64) * ldb + ak;

    float4 ra0, ra1, rb0, rb1;
    auto ldg = [&](int kt) {
        const int kk = kt * KB;
        ra0 = *(const float4*)(Arow0 + kk);
        ra1 = *(const float4*)(Arow1 + kk);
        rb0 = *(const float4*)(Brow0 + kk);
        rb1 = *(const float4*)(Brow1 + kk);
    };
    auto sts = [&](int buf) {
        s.As[buf][ak + 0][am]      = ra0.x; s.As[buf][ak + 1][am]      = ra0.y;
        s.As[buf][ak + 2][am]      = ra0.z; s.As[buf][ak + 3][am]      = ra0.w;
        s.As[buf][ak + 0][am + 64] = ra1.x; s.As[buf][ak + 1][am + 64] = ra1.y;
        s.As[buf][ak + 2][am + 64] = ra1.z; s.As[buf][ak + 3][am + 64] = ra1.w;
        s.Bs[buf][ak + 0][pb0] = rb0.x; s.Bs[buf][ak + 1][pb0] = rb0.y;
        s.Bs[buf][ak + 2][pb0] = rb0.z; s.Bs[buf][ak + 3][pb0] = rb0.w;
        s.Bs[buf][ak + 0][pb1] = rb1.x; s.Bs[buf][ak + 1][pb1] = rb1.y;
        s.Bs[buf][ak + 2][pb1] = rb1.z; s.Bs[buf][ak + 3][pb1] = rb1.w;
    };

    ldg(0); sts(0);
    __syncthreads();
    for (int kt = 0; kt < nk; ++kt) {
        const int cur = kt & 1;
        if (kt + 1 < nk) ldg(kt + 1);
        #pragma unroll
        for (int k = 0; k < KB; ++k) {
            ulonglong2 a01 = *(const ulonglong2*)&s.As[cur][k][tm];
            ulonglong2 a23 = *(const ulonglong2*)&s.As[cur][k][tm + 4];
            float4 b0 = *(const float4*)&s.Bs[cur][k][ptn];
            float4 b1 = *(const float4*)&s.Bs[cur][k][ptn + 4];
            ull d0 = dup2(b0.x), d1 = dup2(b0.y), d2 = dup2(b0.z), d3 = dup2(b0.w);
            ull d4 = dup2(b1.x), d5 = dup2(b1.y), d6 = dup2(b1.z), d7 = dup2(b1.w);
            ffma2(acc[0][0], a01.x, d0); ffma2(acc[0][1], a01.x, d1);
            ffma2(acc[0][2], a01.x, d2); ffma2(acc[0][3], a01.x, d3);
            ffma2(acc[0][4], a01.x, d4); ffma2(acc[0][5], a01.x, d5);
            ffma2(acc[0][6], a01.x, d6); ffma2(acc[0][7], a01.x, d7);
            ffma2(acc[1][0], a01.y, d0); ffma2(acc[1][1], a01.y, d1);
            ffma2(acc[1][2], a01.y, d2); ffma2(acc[1][3], a01.y, d3);
            ffma2(acc[1][4], a01.y, d4); ffma2(acc[1][5], a01.y, d5);
            ffma2(acc[1][6], a01.y, d6); ffma2(acc[1][7], a01.y, d7);
            ffma2(acc[2][0], a23.x, d0); ffma2(acc[2][1], a23.x, d1);
            ffma2(acc[2][2], a23.x, d2); ffma2(acc[2][3], a23.x, d3);
            ffma2(acc[2][4], a23.x, d4); ffma2(acc[2][5], a23.x, d5);
            ffma2(acc[2][6], a23.x, d6); ffma2(acc[2][7], a23.x, d7);
            ffma2(acc[3][0], a23.y, d0); ffma2(acc[3][1], a23.y, d1);
            ffma2(acc[3][2], a23.y, d2); ffma2(acc[3][3], a23.y, d3);
            ffma2(acc[3][4], a23.y, d4); ffma2(acc[3][5], a23.y, d5);
            ffma2(acc[3][6], a23.y, d6); ffma2(acc[3][7], a23.y, d7);
        }
        if (kt + 1 < nk) sts(cur ^ 1);
        __syncthreads();
    }
}

__global__ void __launch_bounds__(NTH, 1)
gemm128(const float* __restrict__ A, int lda,
        const float* __restrict__ B, int ldb,
        float* __restrict__ C, int ldc,
        const float* __restrict__ bias, int K)
{
    __shared__ SmemT s;
    const int tid   = threadIdx.x;
    const int nbase = blockIdx.x * 128;
    const int mbase = blockIdx.y * 128;

    ull acc[4][8];
    #pragma unroll
    for (int p = 0; p < 4; ++p)
        #pragma unroll
        for (int n = 0; n < 8; ++n) acc[p][n] = 0ull;

    gemm_tile(s, A + (size_t)mbase * lda, lda, B + (size_t)nbase * ldb, ldb, K / KB, acc);

    const int tm = (tid >> 4) * 8;
    const int tn = (tid & 15) * 8;
    float bv[8];
    #pragma unroll
    for (int n = 0; n < 8; ++n) bv[n] = bias[nbase + tn + n];

    #pragma unroll
    for (int p = 0; p < 4; ++p) {
        float lo[8], hi[8];
        #pragma unroll
        for (int n = 0; n < 8; ++n) {
            unpack2(lo[n], hi[n], acc[p][n]);
            lo[n] += bv[n]; hi[n] += bv[n];
        }
        const int r0 = mbase + tm + 2 * p;
        float* c0 = C + (size_t)r0 * ldc + nbase + tn;
        float* c1 = c0 + ldc;
        *(float4*)(c0)     = make_float4(lo[0], lo[1], lo[2], lo[3]);
        *(float4*)(c0 + 4) = make_float4(lo[4], lo[5], lo[6], lo[7]);
        *(float4*)(c1)     = make_float4(hi[0], hi[1], hi[2], hi[3]);
        *(float4*)(c1 + 4) = make_float4(hi[4], hi[5], hi[6], hi[7]);
    }
}

__global__ void reset_ctr_kernel()
{
    const int i = blockIdx.x * blockDim.x + threadIdx.x;
    if (i < TT * NTILES) ((int*)g_ctr_tile)[i] = 0;
    if (i < TT) g_ctr_step[i] = 0;
}

__global__ void copy_h_kernel(float* __restrict__ dst)
{
    const int idx = blockIdx.x * blockDim.x + threadIdx.x;
    dst[idx] = g_hall[(size_t)(TT - 1) * BH + idx];
}

extern "C" void kernel_launch(void* const* d_in, const int* in_sizes, int n_in,
                              void* d_out, int out_size)
{
    (void)in_sizes; (void)n_in;
    const int*   x   = (const int*)  d_in[0];
    const float* emb = (const float*)d_in[1];
    const float* Wi  = (const float*)d_in[2];
    const float* bi  = (const float*)d_in[3];
    const float* Wh  = (const float*)d_in[4];
    const float* bh  = (const float*)d_in[5];
    const float* Wo  = (const float*)d_in[6];
    const float* bo  = (const float*)d_in[7];
    float* out = (float*)d_out;

    float* g_P_ptr = nullptr;
    cudaGetSymbolAddress((void**)&g_P_ptr, g_P);

    cudaFuncSetAttribute(scan_mma,     cudaFuncAttributeMaxDynamicSharedMemorySize, SMEM_TC);
    cudaFuncSetAttribute(gemm_out_mma, cudaFuncAttributeMaxDynamicSharedMemorySize, SMEM_TC);

    // Phase 1: P = emb @ Wi^T + bi   [512 x 2048], K=512 (exact fp32)
    gemm128<<<dim3(HH / 128, VV / 128), NTH>>>(emb, VV, Wi, VV, g_P_ptr, HH, bi, VV);

    // Phase 2: persistent mma.sync scan (all 1024 steps, one launch)
    scan_mma<<<dim3(NTILES, KSPLIT), NTH, SMEM_TC>>>(x, Wh, bh);

    // Reset spin counters for the next replay
    reset_ctr_kernel<<<(TT * NTILES + NTH - 1) / NTH, NTH>>>();

    // Phase 3: out = h_all @ Wo^T + bo   [131072 x 512], K=2048 (mma.sync)
    gemm_out_mma<<<dim3(OO / 128, (TT * BB) / 128), NTH, SMEM_TC>>>(Wo, bo, out);

    // Second output: final hidden state h_{T-1}  [B, H]
    if ((long long)out_size >= (long long)(TBO + (size_t)BH))
        copy_h_kernel<<<BH / NTH, NTH>>>(out + TBO);
}

// round 9
// speedup vs baseline: 1.6353x; 1.3625x over previous
#include <cuda_runtime.h>
#include <cuda_bf16.h>
#include <math.h>
#include <cstdint>

// Problem dims
#define TT 1024
#define BB 128
#define VV 512
#define HH 2048
#define OO 512

constexpr int NTH    = 256;
constexpr int KSPLIT = 8;
constexpr int NTILES = HH / 128;     // 16
constexpr int KCH    = HH / KSPLIT;  // 256
constexpr int KSTAGE = 32;           // fp32 K-depth per stage

constexpr int    BH  = BB * HH;
constexpr size_t TBH = (size_t)TT * BH;
constexpr size_t TBO = (size_t)TT * BB * OO;

// Padded SMEM tile geometry: 128 rows x 16 data words (32 bf16) + 4 pad
constexpr int TW     = 20;                  // words per row
constexpr int TILE_W = 128 * TW;            // 2560 words per tile
constexpr int TILE_B = TILE_W * 4;          // 10240 bytes per tile

// Scan smem: A dbuf 4 tiles + Wh stationary 16 tiles = 20 tiles
constexpr int SMEM_SCAN = 20 * TILE_B;      // 204800 B
// Phase-3 smem: A dbuf 4 + B dbuf 4 = 8 tiles
constexpr int SMEM_P3   = 8 * TILE_B;       // 81920 B

// -------- device scratch --------
__device__ float g_P[VV * HH];
__device__ float g_hall[TBH];
__device__ float g_part[KSPLIT * (size_t)BH];
__device__ int   g_ctr_tile[TT][NTILES];
__device__ int   g_ctr_step[TT];
// Pre-split weights, tiled [slice][stage*2+hl][row(128)][word(16)]
__device__ uint4 g_whsplit4[(size_t)128 * 16 * 512];   // 16 MB
__device__ uint4 g_wosplit4[(size_t)4 * 128 * 512];    //  4 MB

// ============================================================================
// bf16x2 split + mma.sync + ldmatrix helpers
// ============================================================================
__device__ __forceinline__ void split2(float v0, float v1,
                                       uint32_t& whi, uint32_t& wlo) {
    __nv_bfloat16 h0 = __float2bfloat16_rn(v0);
    __nv_bfloat16 h1 = __float2bfloat16_rn(v1);
    __nv_bfloat16 l0 = __float2bfloat16_rn(v0 - __bfloat162float(h0));
    __nv_bfloat16 l1 = __float2bfloat16_rn(v1 - __bfloat162float(h1));
    whi = ((uint32_t)__bfloat16_as_ushort(h1) << 16) | __bfloat16_as_ushort(h0);
    wlo = ((uint32_t)__bfloat16_as_ushort(l1) << 16) | __bfloat16_as_ushort(l0);
}

__device__ __forceinline__ void mma_bf16(float* d, const uint32_t* a,
                                         const uint32_t* b) {
    asm volatile(
        "mma.sync.aligned.m16n8k16.row.col.f32.bf16.bf16.f32 "
        "{%0,%1,%2,%3}, {%4,%5,%6,%7}, {%8,%9}, {%0,%1,%2,%3};"
        : "+f"(d[0]), "+f"(d[1]), "+f"(d[2]), "+f"(d[3])
        : "r"(a[0]), "r"(a[1]), "r"(a[2]), "r"(a[3]), "r"(b[0]), "r"(b[1]));
}

__device__ __forceinline__ void ldsm4(uint32_t* r, uint32_t addr) {
    asm volatile("ldmatrix.sync.aligned.m8n8.x4.shared.b16 {%0,%1,%2,%3}, [%4];"
                 : "=r"(r[0]), "=r"(r[1]), "=r"(r[2]), "=r"(r[3]) : "r"(addr));
}

__device__ __forceinline__ uint32_t smem_u32(const void* p) {
    return (uint32_t)__cvta_generic_to_shared(p);
}

// ============================================================================
// MMA stage via ldmatrix: warp tile 32 (M) x 64 (N), K=32, 3-product bf16x2.
// Tile byte-addrs a_hi/a_lo (A: 128xK) and b_hi/b_lo (B: 128 n-rows x K).
// ============================================================================
__device__ __forceinline__ void mma_stage_ldsm(
    uint32_t a_hi, uint32_t a_lo, uint32_t b_hi, uint32_t b_lo,
    int wrow, int wcol, int lane, float (&d)[2][8][4])
{
    const int arow = (lane & 7) + ((lane >> 3) & 1) * 8;
    const int acol = ((lane >> 4) & 1) * 4;
    const int brow = (lane & 7) + ((lane >> 4) & 1) * 8;
    const int bcol = ((lane >> 3) & 1) * 4;
    #pragma unroll
    for (int kk = 0; kk < 2; ++kk) {
        uint32_t ah[2][4], al[2][4];
        #pragma unroll
        for (int m = 0; m < 2; ++m) {
            const uint32_t off =
                (uint32_t)(((wrow + m * 16 + arow) * TW + kk * 8 + acol) * 4);
            ldsm4(ah[m], a_hi + off);
            ldsm4(al[m], a_lo + off);
        }
        #pragma unroll
        for (int np = 0; np < 4; ++np) {
            const uint32_t off =
                (uint32_t)(((wcol + np * 16 + brow) * TW + kk * 8 + bcol) * 4);
            uint32_t bh[4], bl[4];
            ldsm4(bh, b_hi + off);
            ldsm4(bl, b_lo + off);
            #pragma unroll
            for (int m = 0; m < 2; ++m) {
                mma_bf16(d[m][2 * np],     ah[m], &bh[0]);   // hi*hi
                mma_bf16(d[m][2 * np],     ah[m], &bl[0]);   // hi*lo
                mma_bf16(d[m][2 * np],     al[m], &bh[0]);   // lo*hi
                mma_bf16(d[m][2 * np + 1], ah[m], &bh[2]);
                mma_bf16(d[m][2 * np + 1], ah[m], &bl[2]);
                mma_bf16(d[m][2 * np + 1], al[m], &bh[2]);
            }
        }
    }
}

// A producer: thread covers row tid>>1, 16 floats at (tid&1)*16.
struct ARegs { float4 ra[4]; };

__device__ __forceinline__ void a_ldg(ARegs& g, const float* __restrict__ Asrc,
                                      int prow, int pcol, int s)
{
    const float* ap = Asrc + (size_t)prow * HH + pcol + s * KSTAGE;
    #pragma unroll
    for (int i = 0; i < 4; ++i) g.ra[i] = *(const float4*)(ap + 4 * i);
}

__device__ __forceinline__ void a_sts(uint32_t* sm, int buf, const ARegs& g,
                                      int prow, int pcw)
{
    uint32_t* hi = sm + (buf * 2 + 0) * TILE_W + prow * TW + pcw;
    uint32_t* lo = sm + (buf * 2 + 1) * TILE_W + prow * TW + pcw;
    #pragma unroll
    for (int i = 0; i < 4; ++i) {
        uint32_t h0, l0, h1, l1;
        split2(g.ra[i].x, g.ra[i].y, h0, l0);
        split2(g.ra[i].z, g.ra[i].w, h1, l1);
        *(uint2*)(hi + 2 * i) = make_uint2(h0, h1);
        *(uint2*)(lo + 2 * i) = make_uint2(l0, l1);
    }
}

// ============================================================================
// Weight pre-split kernels (run once per launch; tiny)
// ============================================================================
__global__ void presplit_wh(const float* __restrict__ Wh)
{
    const int idx = blockIdx.x * blockDim.x + threadIdx.x;  // < 128*8*128*16
    const int w     = idx & 15;
    const int row   = (idx >> 4) & 127;
    const int s     = (idx >> 11) & 7;
    const int slice = idx >> 14;          // j*8 + z
    const int j = slice >> 3, z = slice & 7;
    const int n = j * 128 + row;
    const int k = z * 256 + s * 32 + w * 2;
    uint32_t whi, wlo;
    split2(Wh[(size_t)n * HH + k], Wh[(size_t)n * HH + k + 1], whi, wlo);
    uint32_t* dst = (uint32_t*)g_whsplit4;
    const size_t tb = (((size_t)slice * 16 + s * 2) * 128 + row) * 16 + w;
    dst[tb] = whi;
    dst[tb + 128 * 16] = wlo;   // next tile (lo)
}

__global__ void presplit_wo(const float* __restrict__ Wo)
{
    const int idx = blockIdx.x * blockDim.x + threadIdx.x;  // < 4*64*128*16
    const int w   = idx & 15;
    const int row = (idx >> 4) & 127;
    const int s   = (idx >> 11) & 63;
    const int nj  = idx >> 17;
    const int n = nj * 128 + row;
    const int k = s * 32 + w * 2;
    uint32_t whi, wlo;
    split2(Wo[(size_t)n * HH + k], Wo[(size_t)n * HH + k + 1], whi, wlo);
    uint32_t* dst = (uint32_t*)g_wosplit4;
    const size_t tb = (((size_t)nj * 128 + s * 2) * 128 + row) * 16 + w;
    dst[tb] = whi;
    dst[tb + 128 * 16] = wlo;
}

// ============================================================================
// Persistent scan kernel: Wh stationary in SMEM, ldmatrix feeds, bf16x2 MMA.
// grid (16 N-tiles, 8 K-splits) = 128 CTAs, single wave.
// ============================================================================
__global__ void __launch_bounds__(NTH, 1)
scan_mma(const int* __restrict__ x,
         const float* __restrict__ bh)
{
    extern __shared__ uint32_t sm[];
    const uint32_t smaddr = smem_u32(sm);

    const int tid  = threadIdx.x;
    const int wid  = tid >> 5;
    const int lane = tid & 31;
    const int j    = blockIdx.x;
    const int z    = blockIdx.y;
    const int nbase = j * 128;
    const int k0    = z * KCH;

    const int wrow = (wid & 3) * 32;
    const int wcol = (wid >> 2) * 64;
    const int prow = tid >> 1;
    const int pcol = (tid & 1) * 16;
    const int pcw  = (tid & 1) * 8;

    const int rrow  = tid >> 1;
    const int cbase = nbase + z * 16 + (tid & 1) * 8;

    // ---- load this CTA's Wh slice (pre-split) into stationary SMEM tiles ----
    {
        const uint4* wsrc = g_whsplit4 + (size_t)(j * 8 + z) * 16 * 512;
        for (int r = tid; r < 16 * 128; r += NTH) {
            const int tile = r >> 7;
            const int row  = r & 127;
            uint32_t* dst = sm + (4 + tile) * TILE_W + row * TW;
            const uint4* s4 = wsrc + (size_t)r * 4;
            #pragma unroll
            for (int q = 0; q < 4; ++q)
                *(uint4*)(dst + 4 * q) = s4[q];
        }
    }

    // ---- t = 0: h_0 = tanh(P[x_0] + bh) ----
    {
        const float* Pr = g_P + (size_t)x[rrow] * HH + cbase;
        float4 p0 = *(const float4*)(Pr);
        float4 p1 = *(const float4*)(Pr + 4);
        float4 b0 = *(const float4*)(bh + cbase);
        float4 b1 = *(const float4*)(bh + cbase + 4);
        float* dst = g_hall + (size_t)rrow * HH + cbase;
        *(float4*)(dst)     = make_float4(tanhf(p0.x + b0.x), tanhf(p0.y + b0.y),
                                          tanhf(p0.z + b0.z), tanhf(p0.w + b0.w));
        *(float4*)(dst + 4) = make_float4(tanhf(p1.x + b1.x), tanhf(p1.y + b1.y),
                                          tanhf(p1.z + b1.z), tanhf(p1.w + b1.w));
        __threadfence();
        __syncthreads();
        if (tid == 0) {
            atomicAdd(&g_ctr_step[0], 1);
            while (*(volatile int*)&g_ctr_step[0] < 128) __nanosleep(40);
            __threadfence();
        }
        __syncthreads();
    }

    for (int t = 1; t < TT; ++t) {
        const float* Asrc = g_hall + (size_t)(t - 1) * BH + k0;

        float d[2][8][4];
        #pragma unroll
        for (int m = 0; m < 2; ++m)
            #pragma unroll
            for (int n = 0; n < 8; ++n)
                #pragma unroll
                for (int q = 0; q < 4; ++q) d[m][n][q] = 0.0f;

        ARegs g;
        a_ldg(g, Asrc, prow, pcol, 0);
        a_sts(sm, 0, g, prow, pcw);
        __syncthreads();

        constexpr int NS = KCH / KSTAGE;   // 8 stages
        #pragma unroll 1
        for (int s = 0; s < NS; ++s) {
            const int cur = s & 1;
            if (s + 1 < NS) a_ldg(g, Asrc, prow, pcol, s + 1);
            mma_stage_ldsm(smaddr + (cur * 2 + 0) * TILE_B,
                           smaddr + (cur * 2 + 1) * TILE_B,
                           smaddr + (4 + s * 2 + 0) * TILE_B,
                           smaddr + (4 + s * 2 + 1) * TILE_B,
                           wrow, wcol, lane, d);
            if (s + 1 < NS) {
                __syncthreads();              // A(cur^1) fully consumed last iter
                a_sts(sm, cur ^ 1, g, prow, pcw);
            }
            __syncthreads();
        }

        // store split-K partial plane z
        {
            float* dst = g_part + (size_t)z * BH;
            #pragma unroll
            for (int m = 0; m < 2; ++m)
                #pragma unroll
                for (int n = 0; n < 8; ++n) {
                    const int r0 = wrow + m * 16 + (lane >> 2);
                    const int c0 = nbase + wcol + n * 8 + (lane & 3) * 2;
                    *(float2*)(dst + (size_t)r0 * HH + c0) =
                        make_float2(d[m][n][0], d[m][n][1]);
                    *(float2*)(dst + (size_t)(r0 + 8) * HH + c0) =
                        make_float2(d[m][n][2], d[m][n][3]);
                }
        }
        __threadfence();
        __syncthreads();

        // per-N-tile barrier: all 8 split-K planes of tile j present
        if (tid == 0) {
            atomicAdd(&g_ctr_tile[t][j], 1);
            while (*(volatile int*)&g_ctr_tile[t][j] < KSPLIT) { }
            __threadfence();
        }
        __syncthreads();

        // distributed reduce + tanh over this CTA's 128x16 slice
        {
            const float* Pr = g_P + (size_t)x[(size_t)t * BB + rrow] * HH + cbase;
            float4 p0 = *(const float4*)(Pr);
            float4 p1 = *(const float4*)(Pr + 4);
            float4 b0 = *(const float4*)(bh + cbase);
            float4 b1 = *(const float4*)(bh + cbase + 4);
            float4 v0 = make_float4(p0.x + b0.x, p0.y + b0.y, p0.z + b0.z, p0.w + b0.w);
            float4 v1 = make_float4(p1.x + b1.x, p1.y + b1.y, p1.z + b1.z, p1.w + b1.w);
            const size_t off = (size_t)rrow * HH + cbase;
            #pragma unroll
            for (int z2 = 0; z2 < KSPLIT; ++z2) {
                float4 u0 = __ldcg((const float4*)(g_part + (size_t)z2 * BH + off));
                float4 u1 = __ldcg((const float4*)(g_part + (size_t)z2 * BH + off + 4));
                v0.x += u0.x; v0.y += u0.y; v0.z += u0.z; v0.w += u0.w;
                v1.x += u1.x; v1.y += u1.y; v1.z += u1.z; v1.w += u1.w;
            }
            float* dst = g_hall + (size_t)t * BH + off;
            *(float4*)(dst)     = make_float4(tanhf(v0.x), tanhf(v0.y),
                                              tanhf(v0.z), tanhf(v0.w));
            *(float4*)(dst + 4) = make_float4(tanhf(v1.x), tanhf(v1.y),
                                              tanhf(v1.z), tanhf(v1.w));
        }
        __threadfence();
        __syncthreads();

        // global barrier: h_t complete before anyone loads it at t+1
        if (tid == 0) {
            atomicAdd(&g_ctr_step[t], 1);
            while (*(volatile int*)&g_ctr_step[t] < 128) __nanosleep(40);
            __threadfence();
        }
        __syncthreads();
    }
}

// ============================================================================
// Phase-3 GEMM: out = h_all @ Wo^T + bo.  A converted in-flight; B copied
// from pre-split tiles.  grid (4 N-tiles, 1024 M-tiles), K=2048 -> 64 stages.
// ============================================================================
__global__ void __launch_bounds__(NTH, 1)
gemm_out_mma(const float* __restrict__ bo,
             float* __restrict__ out)
{
    extern __shared__ uint32_t sm[];
    const uint32_t smaddr = smem_u32(sm);

    const int tid  = threadIdx.x;
    const int wid  = tid >> 5;
    const int lane = tid & 31;
    const int nj   = blockIdx.x;
    const int nbase = nj * 128;
    const size_t mbase = (size_t)blockIdx.y * 128;

    const int wrow = (wid & 3) * 32;
    const int wcol = (wid >> 2) * 64;
    const int prow = tid >> 1;
    const int pcol = (tid & 1) * 16;
    const int pcw  = (tid & 1) * 8;
    const int q0   = (tid & 1) * 2;

    const float* Asrc = g_hall + mbase * HH;
    const uint4* bsrc = g_wosplit4 + (size_t)nj * 128 * 512;

    float d[2][8][4];
    #pragma unroll
    for (int m = 0; m < 2; ++m)
        #pragma unroll
        for (int n = 0; n < 8; ++n)
            #pragma unroll
            for (int q = 0; q < 4; ++q) d[m][n][q] = 0.0f;

    ARegs g;
    uint4 bw[4];
    auto b_ldg = [&](int s) {
        const uint4* p = bsrc + (size_t)(s * 2) * 512 + (size_t)prow * 4 + q0;
        bw[0] = p[0];  bw[1] = p[1];          // hi tile, 2 uint4
        bw[2] = p[512]; bw[3] = p[513];       // lo tile
    };
    auto b_sts = [&](int buf) {
        uint32_t* hi = sm + (4 + buf * 2 + 0) * TILE_W + prow * TW + q0 * 4;
        uint32_t* lo = sm + (4 + buf * 2 + 1) * TILE_W + prow * TW + q0 * 4;
        *(uint4*)(hi)     = bw[0];
        *(uint4*)(hi + 4) = bw[1];
        *(uint4*)(lo)     = bw[2];
        *(uint4*)(lo + 4) = bw[3];
    };

    a_ldg(g, Asrc, prow, pcol, 0);
    b_ldg(0);
    a_sts(sm, 0, g, prow, pcw);
    b_sts(0);
    __syncthreads();

    constexpr int NS = HH / KSTAGE;   // 64 stages
    #pragma unroll 1
    for (int s = 0; s < NS; ++s) {
        const int cur = s & 1;
        if (s + 1 < NS) { a_ldg(g, Asrc, prow, pcol, s + 1); b_ldg(s + 1); }
        mma_stage_ldsm(smaddr + (cur * 2 + 0) * TILE_B,
                       smaddr + (cur * 2 + 1) * TILE_B,
                       smaddr + (4 + cur * 2 + 0) * TILE_B,
                       smaddr + (4 + cur * 2 + 1) * TILE_B,
                       wrow, wcol, lane, d);
        if (s + 1 < NS) {
            __syncthreads();
            a_sts(sm, cur ^ 1, g, prow, pcw);
            b_sts(cur ^ 1);
        }
        __syncthreads();
    }

    // epilogue: + bias, store
    #pragma unroll
    for (int m = 0; m < 2; ++m)
        #pragma unroll
        for (int n = 0; n < 8; ++n) {
            const int r0 = wrow + m * 16 + (lane >> 2);
            const int c0 = nbase + wcol + n * 8 + (lane & 3) * 2;
            const float2 bv = *(const float2*)(bo + c0);
            *(float2*)(out + (mbase + r0) * OO + c0) =
                make_float2(d[m][n][0] + bv.x, d[m][n][1] + bv.y);
            *(float2*)(out + (mbase + r0 + 8) * OO + c0) =
                make_float2(d[m][n][2] + bv.x, d[m][n][3] + bv.y);
        }
}

// ============================================================================
// Phase-1 fp32 FFMA2 GEMM (exact; verified R6 code)
// ============================================================================
typedef unsigned long long ull;
__device__ __forceinline__ void ffma2(ull& d, ull a, ull b) {
    asm("fma.rn.f32x2 %0, %1, %2, %3;" : "=l"(d) : "l"(a), "l"(b), "l"(d));
}
__device__ __forceinline__ void unpack2(float& lo, float& hi, ull v) {
    asm("mov.b64 {%0,%1}, %2;" : "=f"(lo), "=f"(hi) : "l"(v));
}
__device__ __forceinline__ ull dup2(float v) {
    ull r; asm("mov.b64 %0, {%1,%1};" : "=l"(r) : "f"(v)); return r;
}
constexpr int KB = 16;
struct SmemT {
    float As[2][KB][132];
    float Bs[2][KB][140];
};
__device__ __forceinline__ int skew(int n) { return n + ((n >> 5) << 2); }

__device__ __forceinline__ void gemm_tile(SmemT& s,
    const float* __restrict__ Ag, int lda,
    const float* __restrict__ Bg, int ldb,
    int nk, ull (&acc)[4][8])
{
    const int tid = threadIdx.x;
    const int am  = tid >> 2;
    const int ak  = (tid & 3) * 4;
    const int tm  = (tid >> 4) * 8;
    const int tn  = (tid & 15) * 8;
    const int ptn = skew(tn);
    const int pb0 = skew(am);
    const int pb1 = skew(am + 64);

    const float* Arow0 = Ag + (size_t)am        * lda + ak;
    const float* Arow1 = Ag + (size_t)(am + 64) * lda + ak;
    const float* Brow0 = Bg + (size_t)am        * ldb + ak;
    const float* Brow1 = Bg + (size_t)(am + 64) * ldb + ak;

    float4 ra0, ra1, rb0, rb1;
    auto ldg = [&](int kt) {
        const int kk = kt * KB;
        ra0 = *(const float4*)(Arow0 + kk);
        ra1 = *(const float4*)(Arow1 + kk);
        rb0 = *(const float4*)(Brow0 + kk);
        rb1 = *(const float4*)(Brow1 + kk);
    };
    auto sts = [&](int buf) {
        s.As[buf][ak + 0][am]      = ra0.x; s.As[buf][ak + 1][am]      = ra0.y;
        s.As[buf][ak + 2][am]      = ra0.z; s.As[buf][ak + 3][am]      = ra0.w;
        s.As[buf][ak + 0][am + 64] = ra1.x; s.As[buf][ak + 1][am + 64] = ra1.y;
        s.As[buf][ak + 2][am + 64] = ra1.z; s.As[buf][ak + 3][am + 64] = ra1.w;
        s.Bs[buf][ak + 0][pb0] = rb0.x; s.Bs[buf][ak + 1][pb0] = rb0.y;
        s.Bs[buf][ak + 2][pb0] = rb0.z; s.Bs[buf][ak + 3][pb0] = rb0.w;
        s.Bs[buf][ak + 0][pb1] = rb1.x; s.Bs[buf][ak + 1][pb1] = rb1.y;
        s.Bs[buf][ak + 2][pb1] = rb1.z; s.Bs[buf][ak + 3][pb1] = rb1.w;
    };

    ldg(0); sts(0);
    __syncthreads();
    for (int kt = 0; kt < nk; ++kt) {
        const int cur = kt & 1;
        if (kt + 1 < nk) ldg(kt + 1);
        #pragma unroll
        for (int k = 0; k < KB; ++k) {
            ulonglong2 a01 = *(const ulonglong2*)&s.As[cur][k][tm];
            ulonglong2 a23 = *(const ulonglong2*)&s.As[cur][k][tm + 4];
            float4 b0 = *(const float4*)&s.Bs[cur][k][ptn];
            float4 b1 = *(const float4*)&s.Bs[cur][k][ptn + 4];
            ull d0 = dup2(b0.x), d1 = dup2(b0.y), d2 = dup2(b0.z), d3 = dup2(b0.w);
            ull d4 = dup2(b1.x), d5 = dup2(b1.y), d6 = dup2(b1.z), d7 = dup2(b1.w);
            ffma2(acc[0][0], a01.x, d0); ffma2(acc[0][1], a01.x, d1);
            ffma2(acc[0][2], a01.x, d2); ffma2(acc[0][3], a01.x, d3);
            ffma2(acc[0][4], a01.x, d4); ffma2(acc[0][5], a01.x, d5);
            ffma2(acc[0][6], a01.x, d6); ffma2(acc[0][7], a01.x, d7);
            ffma2(acc[1][0], a01.y, d0); ffma2(acc[1][1], a01.y, d1);
            ffma2(acc[1][2], a01.y, d2); ffma2(acc[1][3], a01.y, d3);
            ffma2(acc[1][4], a01.y, d4); ffma2(acc[1][5], a01.y, d5);
            ffma2(acc[1][6], a01.y, d6); ffma2(acc[1][7], a01.y, d7);
            ffma2(acc[2][0], a23.x, d0); ffma2(acc[2][1], a23.x, d1);
            ffma2(acc[2][2], a23.x, d2); ffma2(acc[2][3], a23.x, d3);
            ffma2(acc[2][4], a23.x, d4); ffma2(acc[2][5], a23.x, d5);
            ffma2(acc[2][6], a23.x, d6); ffma2(acc[2][7], a23.x, d7);
            ffma2(acc[3][0], a23.y, d0); ffma2(acc[3][1], a23.y, d1);
            ffma2(acc[3][2], a23.y, d2); ffma2(acc[3][3], a23.y, d3);
            ffma2(acc[3][4], a23.y, d4); ffma2(acc[3][5], a23.y, d5);
            ffma2(acc[3][6], a23.y, d6); ffma2(acc[3][7], a23.y, d7);
        }
        if (kt + 1 < nk) sts(cur ^ 1);
        __syncthreads();
    }
}

__global__ void __launch_bounds__(NTH, 1)
gemm128(const float* __restrict__ A, int lda,
        const float* __restrict__ B, int ldb,
        float* __restrict__ C, int ldc,
        const float* __restrict__ bias, int K)
{
    __shared__ SmemT s;
    const int tid   = threadIdx.x;
    const int nbase = blockIdx.x * 128;
    const int mbase = blockIdx.y * 128;

    ull acc[4][8];
    #pragma unroll
    for (int p = 0; p < 4; ++p)
        #pragma unroll
        for (int n = 0; n < 8; ++n) acc[p][n] = 0ull;

    gemm_tile(s, A + (size_t)mbase * lda, lda, B + (size_t)nbase * ldb, ldb, K / KB, acc);

    const int tm = (tid >> 4) * 8;
    const int tn = (tid & 15) * 8;
    float bv[8];
    #pragma unroll
    for (int n = 0; n < 8; ++n) bv[n] = bias[nbase + tn + n];

    #pragma unroll
    for (int p = 0; p < 4; ++p) {
        float lo[8], hi[8];
        #pragma unroll
        for (int n = 0; n < 8; ++n) {
            unpack2(lo[n], hi[n], acc[p][n]);
            lo[n] += bv[n]; hi[n] += bv[n];
        }
        const int r0 = mbase + tm + 2 * p;
        float* c0 = C + (size_t)r0 * ldc + nbase + tn;
        float* c1 = c0 + ldc;
        *(float4*)(c0)     = make_float4(lo[0], lo[1], lo[2], lo[3]);
        *(float4*)(c0 + 4) = make_float4(lo[4], lo[5], lo[6], lo[7]);
        *(float4*)(c1)     = make_float4(hi[0], hi[1], hi[2], hi[3]);
        *(float4*)(c1 + 4) = make_float4(hi[4], hi[5], hi[6], hi[7]);
    }
}

__global__ void reset_ctr_kernel()
{
    const int i = blockIdx.x * blockDim.x + threadIdx.x;
    if (i < TT * NTILES) ((int*)g_ctr_tile)[i] = 0;
    if (i < TT) g_ctr_step[i] = 0;
}

__global__ void copy_h_kernel(float* __restrict__ dst)
{
    const int idx = blockIdx.x * blockDim.x + threadIdx.x;
    dst[idx] = g_hall[(size_t)(TT - 1) * BH + idx];
}

extern "C" void kernel_launch(void* const* d_in, const int* in_sizes, int n_in,
                              void* d_out, int out_size)
{
    (void)in_sizes; (void)n_in;
    const int*   x   = (const int*)  d_in[0];
    const float* emb = (const float*)d_in[1];
    const float* Wi  = (const float*)d_in[2];
    const float* bi  = (const float*)d_in[3];
    const float* Wh  = (const float*)d_in[4];
    const float* bh  = (const float*)d_in[5];
    const float* Wo  = (const float*)d_in[6];
    const float* bo  = (const float*)d_in[7];
    float* out = (float*)d_out;

    float* g_P_ptr = nullptr;
    cudaGetSymbolAddress((void**)&g_P_ptr, g_P);

    cudaFuncSetAttribute(scan_mma,     cudaFuncAttributeMaxDynamicSharedMemorySize, SMEM_SCAN);
    cudaFuncSetAttribute(gemm_out_mma, cudaFuncAttributeMaxDynamicSharedMemorySize, SMEM_P3);

    // Pre-split weights into bf16 hi/lo tiled layout (one-time per launch)
    presplit_wh<<<(128 * 8 * 128 * 16) / NTH, NTH>>>(Wh);
    presplit_wo<<<(4 * 64 * 128 * 16) / NTH, NTH>>>(Wo);

    // Phase 1: P = emb @ Wi^T + bi   [512 x 2048], K=512 (exact fp32)
    gemm128<<<dim3(HH / 128, VV / 128), NTH>>>(emb, VV, Wi, VV, g_P_ptr, HH, bi, VV);

    // Phase 2: persistent mma.sync scan (all 1024 steps, one launch)
    scan_mma<<<dim3(NTILES, KSPLIT), NTH, SMEM_SCAN>>>(x, bh);

    // Reset spin counters for the next replay
    reset_ctr_kernel<<<(TT * NTILES + NTH - 1) / NTH, NTH>>>();

    // Phase 3: out = h_all @ Wo^T + bo   [131072 x 512], K=2048
    gemm_out_mma<<<dim3(OO / 128, (TT * BB) / 128), NTH, SMEM_P3>>>(bo, out);

    // Second output: final hidden state h_{T-1}  [B, H]
    if ((long long)out_size >= (long long)(TBO + (size_t)BH))
        copy_h_kernel<<<BH / NTH, NTH>>>(out + TBO);
}

// round 10
// speedup vs baseline: 1.6374x; 1.0013x over previous
#include <cuda_runtime.h>
#include <cuda_bf16.h>
#include <math.h>
#include <cstdint>

// Problem dims
#define TT 1024
#define BB 128
#define VV 512
#define HH 2048
#define OO 512

constexpr int NTH    = 256;
constexpr int KSPLIT = 8;
constexpr int NTILES = HH / 128;     // 16
constexpr int KCH    = HH / KSPLIT;  // 256
constexpr int KSTAGE = 32;           // fp32 K-depth per stage

constexpr int    BH  = BB * HH;
constexpr size_t TBH = (size_t)TT * BH;
constexpr size_t TBO = (size_t)TT * BB * OO;

// Padded SMEM tile geometry: 128 rows x 16 data words (32 bf16) + 4 pad
constexpr int TW     = 20;                  // words per row
constexpr int TILE_W = 128 * TW;            // 2560 words per tile
constexpr int TILE_B = TILE_W * 4;          // 10240 bytes per tile

// Scan smem: A dbuf 4 tiles + Wh stationary 16 tiles = 20 tiles
constexpr int SMEM_SCAN = 20 * TILE_B;      // 204800 B
// Phase-3 smem: A dbuf 4 + B dbuf 4 = 8 tiles
constexpr int SMEM_P3   = 8 * TILE_B;       // 81920 B

// -------- device scratch --------
__device__ float g_P[VV * HH];
__device__ float g_hall[TBH];
__device__ float g_part[KSPLIT * (size_t)BH];
__device__ int   g_ctr_tile[TT][NTILES];
__device__ int   g_ctr_step[TT];
// Pre-split weights, tiled [slice][stage*2+hl][row(128)][word(16)]
__device__ uint4 g_whsplit4[(size_t)128 * 16 * 512];   // 16 MB
__device__ uint4 g_wosplit4[(size_t)4 * 128 * 512];    //  4 MB

// ============================================================================
// bf16x2 split + mma.sync + ldmatrix helpers
// ============================================================================
__device__ __forceinline__ void split2(float v0, float v1,
                                       uint32_t& whi, uint32_t& wlo) {
    __nv_bfloat16 h0 = __float2bfloat16_rn(v0);
    __nv_bfloat16 h1 = __float2bfloat16_rn(v1);
    __nv_bfloat16 l0 = __float2bfloat16_rn(v0 - __bfloat162float(h0));
    __nv_bfloat16 l1 = __float2bfloat16_rn(v1 - __bfloat162float(h1));
    whi = ((uint32_t)__bfloat16_as_ushort(h1) << 16) | __bfloat16_as_ushort(h0);
    wlo = ((uint32_t)__bfloat16_as_ushort(l1) << 16) | __bfloat16_as_ushort(l0);
}

__device__ __forceinline__ void mma_bf16(float* d, const uint32_t* a,
                                         const uint32_t* b) {
    asm volatile(
        "mma.sync.aligned.m16n8k16.row.col.f32.bf16.bf16.f32 "
        "{%0,%1,%2,%3}, {%4,%5,%6,%7}, {%8,%9}, {%0,%1,%2,%3};"
        : "+f"(d[0]), "+f"(d[1]), "+f"(d[2]), "+f"(d[3])
        : "r"(a[0]), "r"(a[1]), "r"(a[2]), "r"(a[3]), "r"(b[0]), "r"(b[1]));
}

__device__ __forceinline__ void ldsm4(uint32_t* r, uint32_t addr) {
    asm volatile("ldmatrix.sync.aligned.m8n8.x4.shared.b16 {%0,%1,%2,%3}, [%4];"
                 : "=r"(r[0]), "=r"(r[1]), "=r"(r[2]), "=r"(r[3]) : "r"(addr));
}

__device__ __forceinline__ uint32_t smem_u32(const void* p) {
    return (uint32_t)__cvta_generic_to_shared(p);
}

// ============================================================================
// MMA stage via ldmatrix: warp tile 32 (M) x 64 (N), K=32, 3-product bf16x2.
// Product-major issue order: all hi*hi, then hi*lo, then lo*hi -> 16-MMA
// spacing between same-accumulator HMMAs (kills the RAW chain that capped
// tensor pipe at 29%).  Per-accumulator order (hh, hl, lh per k16) is
// IDENTICAL to the previous kernel -> bit-identical numerics.
// ============================================================================
__device__ __forceinline__ void mma_stage_ldsm(
    uint32_t a_hi, uint32_t a_lo, uint32_t b_hi, uint32_t b_lo,
    int wrow, int wcol, int lane, float (&d)[2][8][4])
{
    const int arow = (lane & 7) + ((lane >> 3) & 1) * 8;
    const int acol = ((lane >> 4) & 1) * 4;
    const int brow = (lane & 7) + ((lane >> 4) & 1) * 8;
    const int bcol = ((lane >> 3) & 1) * 4;
    #pragma unroll
    for (int kk = 0; kk < 2; ++kk) {
        uint32_t ah[2][4], al[2][4];
        uint32_t bh[4][4], bl[4][4];
        #pragma unroll
        for (int m = 0; m < 2; ++m) {
            const uint32_t off =
                (uint32_t)(((wrow + m * 16 + arow) * TW + kk * 8 + acol) * 4);
            ldsm4(ah[m], a_hi + off);
            ldsm4(al[m], a_lo + off);
        }
        #pragma unroll
        for (int np = 0; np < 4; ++np) {
            const uint32_t off =
                (uint32_t)(((wcol + np * 16 + brow) * TW + kk * 8 + bcol) * 4);
            ldsm4(bh[np], b_hi + off);
            ldsm4(bl[np], b_lo + off);
        }
        // hi*hi wave
        #pragma unroll
        for (int np = 0; np < 4; ++np)
            #pragma unroll
            for (int h = 0; h < 2; ++h)
                #pragma unroll
                for (int m = 0; m < 2; ++m)
                    mma_bf16(d[m][2 * np + h], ah[m], &bh[np][2 * h]);
        // hi*lo wave
        #pragma unroll
        for (int np = 0; np < 4; ++np)
            #pragma unroll
            for (int h = 0; h < 2; ++h)
                #pragma unroll
                for (int m = 0; m < 2; ++m)
                    mma_bf16(d[m][2 * np + h], ah[m], &bl[np][2 * h]);
        // lo*hi wave
        #pragma unroll
        for (int np = 0; np < 4; ++np)
            #pragma unroll
            for (int h = 0; h < 2; ++h)
                #pragma unroll
                for (int m = 0; m < 2; ++m)
                    mma_bf16(d[m][2 * np + h], al[m], &bh[np][2 * h]);
    }
}

// A producer: thread covers row tid>>1, 16 floats at (tid&1)*16.
struct ARegs { float4 ra[4]; };

__device__ __forceinline__ void a_ldg(ARegs& g, const float* __restrict__ Asrc,
                                      int prow, int pcol, int s)
{
    const float* ap = Asrc + (size_t)prow * HH + pcol + s * KSTAGE;
    #pragma unroll
    for (int i = 0; i < 4; ++i) g.ra[i] = *(const float4*)(ap + 4 * i);
}

__device__ __forceinline__ void a_sts(uint32_t* sm, int buf, const ARegs& g,
                                      int prow, int pcw)
{
    uint32_t* hi = sm + (buf * 2 + 0) * TILE_W + prow * TW + pcw;
    uint32_t* lo = sm + (buf * 2 + 1) * TILE_W + prow * TW + pcw;
    #pragma unroll
    for (int i = 0; i < 4; ++i) {
        uint32_t h0, l0, h1, l1;
        split2(g.ra[i].x, g.ra[i].y, h0, l0);
        split2(g.ra[i].z, g.ra[i].w, h1, l1);
        *(uint2*)(hi + 2 * i) = make_uint2(h0, h1);
        *(uint2*)(lo + 2 * i) = make_uint2(l0, l1);
    }
}

// ============================================================================
// Weight pre-split kernels (run once per launch; tiny)
// ============================================================================
__global__ void presplit_wh(const float* __restrict__ Wh)
{
    const int idx = blockIdx.x * blockDim.x + threadIdx.x;  // < 128*8*128*16
    const int w     = idx & 15;
    const int row   = (idx >> 4) & 127;
    const int s     = (idx >> 11) & 7;
    const int slice = idx >> 14;          // j*8 + z
    const int j = slice >> 3, z = slice & 7;
    const int n = j * 128 + row;
    const int k = z * 256 + s * 32 + w * 2;
    uint32_t whi, wlo;
    split2(Wh[(size_t)n * HH + k], Wh[(size_t)n * HH + k + 1], whi, wlo);
    uint32_t* dst = (uint32_t*)g_whsplit4;
    const size_t tb = (((size_t)slice * 16 + s * 2) * 128 + row) * 16 + w;
    dst[tb] = whi;
    dst[tb + 128 * 16] = wlo;   // next tile (lo)
}

__global__ void presplit_wo(const float* __restrict__ Wo)
{
    const int idx = blockIdx.x * blockDim.x + threadIdx.x;  // < 4*64*128*16
    const int w   = idx & 15;
    const int row = (idx >> 4) & 127;
    const int s   = (idx >> 11) & 63;
    const int nj  = idx >> 17;
    const int n = nj * 128 + row;
    const int k = s * 32 + w * 2;
    uint32_t whi, wlo;
    split2(Wo[(size_t)n * HH + k], Wo[(size_t)n * HH + k + 1], whi, wlo);
    uint32_t* dst = (uint32_t*)g_wosplit4;
    const size_t tb = (((size_t)nj * 128 + s * 2) * 128 + row) * 16 + w;
    dst[tb] = whi;
    dst[tb + 128 * 16] = wlo;
}

// ============================================================================
// Persistent scan kernel: Wh stationary in SMEM, ldmatrix feeds, bf16x2 MMA.
// grid (16 N-tiles, 8 K-splits) = 128 CTAs, single wave.
// ============================================================================
__global__ void __launch_bounds__(NTH, 1)
scan_mma(const int* __restrict__ x,
         const float* __restrict__ bh)
{
    extern __shared__ uint32_t sm[];
    const uint32_t smaddr = smem_u32(sm);

    const int tid  = threadIdx.x;
    const int wid  = tid >> 5;
    const int lane = tid & 31;
    const int j    = blockIdx.x;
    const int z    = blockIdx.y;
    const int nbase = j * 128;
    const int k0    = z * KCH;

    const int wrow = (wid & 3) * 32;
    const int wcol = (wid >> 2) * 64;
    const int prow = tid >> 1;
    const int pcol = (tid & 1) * 16;
    const int pcw  = (tid & 1) * 8;

    const int rrow  = tid >> 1;
    const int cbase = nbase + z * 16 + (tid & 1) * 8;

    // ---- load this CTA's Wh slice (pre-split) into stationary SMEM tiles ----
    {
        const uint4* wsrc = g_whsplit4 + (size_t)(j * 8 + z) * 16 * 512;
        for (int r = tid; r < 16 * 128; r += NTH) {
            const int tile = r >> 7;
            const int row  = r & 127;
            uint32_t* dst = sm + (4 + tile) * TILE_W + row * TW;
            const uint4* s4 = wsrc + (size_t)r * 4;
            #pragma unroll
            for (int q = 0; q < 4; ++q)
                *(uint4*)(dst + 4 * q) = s4[q];
        }
    }

    // ---- t = 0: h_0 = tanh(P[x_0] + bh) ----
    {
        const float* Pr = g_P + (size_t)x[rrow] * HH + cbase;
        float4 p0 = *(const float4*)(Pr);
        float4 p1 = *(const float4*)(Pr + 4);
        float4 b0 = *(const float4*)(bh + cbase);
        float4 b1 = *(const float4*)(bh + cbase + 4);
        float* dst = g_hall + (size_t)rrow * HH + cbase;
        *(float4*)(dst)     = make_float4(tanhf(p0.x + b0.x), tanhf(p0.y + b0.y),
                                          tanhf(p0.z + b0.z), tanhf(p0.w + b0.w));
        *(float4*)(dst + 4) = make_float4(tanhf(p1.x + b1.x), tanhf(p1.y + b1.y),
                                          tanhf(p1.z + b1.z), tanhf(p1.w + b1.w));
        __threadfence();
        __syncthreads();
        if (tid == 0) {
            atomicAdd(&g_ctr_step[0], 1);
            while (*(volatile int*)&g_ctr_step[0] < 128) __nanosleep(40);
            __threadfence();
        }
        __syncthreads();
    }

    for (int t = 1; t < TT; ++t) {
        const float* Asrc = g_hall + (size_t)(t - 1) * BH + k0;

        float d[2][8][4];
        #pragma unroll
        for (int m = 0; m < 2; ++m)
            #pragma unroll
            for (int n = 0; n < 8; ++n)
                #pragma unroll
                for (int q = 0; q < 4; ++q) d[m][n][q] = 0.0f;

        ARegs g;
        a_ldg(g, Asrc, prow, pcol, 0);
        a_sts(sm, 0, g, prow, pcw);
        __syncthreads();

        constexpr int NS = KCH / KSTAGE;   // 8 stages
        #pragma unroll 1
        for (int s = 0; s < NS; ++s) {
            const int cur = s & 1;
            if (s + 1 < NS) a_ldg(g, Asrc, prow, pcol, s + 1);
            mma_stage_ldsm(smaddr + (cur * 2 + 0) * TILE_B,
                           smaddr + (cur * 2 + 1) * TILE_B,
                           smaddr + (4 + s * 2 + 0) * TILE_B,
                           smaddr + (4 + s * 2 + 1) * TILE_B,
                           wrow, wcol, lane, d);
            // NOTE: no barrier needed before a_sts(cur^1): the end-of-iteration
            // barrier of step s-1 already ordered every warp past mma(cur^1).
            if (s + 1 < NS) a_sts(sm, cur ^ 1, g, prow, pcw);
            __syncthreads();
        }

        // store split-K partial plane z
        {
            float* dst = g_part + (size_t)z * BH;
            #pragma unroll
            for (int m = 0; m < 2; ++m)
                #pragma unroll
                for (int n = 0; n < 8; ++n) {
                    const int r0 = wrow + m * 16 + (lane >> 2);
                    const int c0 = nbase + wcol + n * 8 + (lane & 3) * 2;
                    *(float2*)(dst + (size_t)r0 * HH + c0) =
                        make_float2(d[m][n][0], d[m][n][1]);
                    *(float2*)(dst + (size_t)(r0 + 8) * HH + c0) =
                        make_float2(d[m][n][2], d[m][n][3]);
                }
        }
        __threadfence();
        __syncthreads();

        // per-N-tile barrier: all 8 split-K planes of tile j present
        if (tid == 0) {
            atomicAdd(&g_ctr_tile[t][j], 1);
            while (*(volatile int*)&g_ctr_tile[t][j] < KSPLIT) { }
            __threadfence();
        }
        __syncthreads();

        // distributed reduce + tanh over this CTA's 128x16 slice
        {
            const float* Pr = g_P + (size_t)x[(size_t)t * BB + rrow] * HH + cbase;
            float4 p0 = *(const float4*)(Pr);
            float4 p1 = *(const float4*)(Pr + 4);
            float4 b0 = *(const float4*)(bh + cbase);
            float4 b1 = *(const float4*)(bh + cbase + 4);
            float4 v0 = make_float4(p0.x + b0.x, p0.y + b0.y, p0.z + b0.z, p0.w + b0.w);
            float4 v1 = make_float4(p1.x + b1.x, p1.y + b1.y, p1.z + b1.z, p1.w + b1.w);
            const size_t off = (size_t)rrow * HH + cbase;
            #pragma unroll
            for (int z2 = 0; z2 < KSPLIT; ++z2) {
                float4 u0 = __ldcg((const float4*)(g_part + (size_t)z2 * BH + off));
                float4 u1 = __ldcg((const float4*)(g_part + (size_t)z2 * BH + off + 4));
                v0.x += u0.x; v0.y += u0.y; v0.z += u0.z; v0.w += u0.w;
                v1.x += u1.x; v1.y += u1.y; v1.z += u1.z; v1.w += u1.w;
            }
            float* dst = g_hall + (size_t)t * BH + off;
            *(float4*)(dst)     = make_float4(tanhf(v0.x), tanhf(v0.y),
                                              tanhf(v0.z), tanhf(v0.w));
            *(float4*)(dst + 4) = make_float4(tanhf(v1.x), tanhf(v1.y),
                                              tanhf(v1.z), tanhf(v1.w));
        }
        __threadfence();
        __syncthreads();

        // global barrier: h_t complete before anyone loads it at t+1
        if (tid == 0) {
            atomicAdd(&g_ctr_step[t], 1);
            while (*(volatile int*)&g_ctr_step[t] < 128) __nanosleep(40);
            __threadfence();
        }
        __syncthreads();
    }
}

// ============================================================================
// Phase-3 GEMM: out = h_all @ Wo^T + bo.  A converted in-flight; B copied
// from pre-split tiles.  grid (4 N-tiles, 1024 M-tiles), K=2048 -> 64 stages.
// ============================================================================
__global__ void __launch_bounds__(NTH, 1)
gemm_out_mma(const float* __restrict__ bo,
             float* __restrict__ out)
{
    extern __shared__ uint32_t sm[];
    const uint32_t smaddr = smem_u32(sm);

    const int tid  = threadIdx.x;
    const int wid  = tid >> 5;
    const int lane = tid & 31;
    const int nj   = blockIdx.x;
    const int nbase = nj * 128;
    const size_t mbase = (size_t)blockIdx.y * 128;

    const int wrow = (wid & 3) * 32;
    const int wcol = (wid >> 2) * 64;
    const int prow = tid >> 1;
    const int pcol = (tid & 1) * 16;
    const int pcw  = (tid & 1) * 8;
    const int q0   = (tid & 1) * 2;

    const float* Asrc = g_hall + mbase * HH;
    const uint4* bsrc = g_wosplit4 + (size_t)nj * 128 * 512;

    float d[2][8][4];
    #pragma unroll
    for (int m = 0; m < 2; ++m)
        #pragma unroll
        for (int n = 0; n < 8; ++n)
            #pragma unroll
            for (int q = 0; q < 4; ++q) d[m][n][q] = 0.0f;

    ARegs g;
    uint4 bw[4];
    auto b_ldg = [&](int s) {
        const uint4* p = bsrc + (size_t)(s * 2) * 512 + (size_t)prow * 4 + q0;
        bw[0] = p[0];  bw[1] = p[1];          // hi tile, 2 uint4
        bw[2] = p[512]; bw[3] = p[513];       // lo tile
    };
    auto b_sts = [&](int buf) {
        uint32_t* hi = sm + (4 + buf * 2 + 0) * TILE_W + prow * TW + q0 * 4;
        uint32_t* lo = sm + (4 + buf * 2 + 1) * TILE_W + prow * TW + q0 * 4;
        *(uint4*)(hi)     = bw[0];
        *(uint4*)(hi + 4) = bw[1];
        *(uint4*)(lo)     = bw[2];
        *(uint4*)(lo + 4) = bw[3];
    };

    a_ldg(g, Asrc, prow, pcol, 0);
    b_ldg(0);
    a_sts(sm, 0, g, prow, pcw);
    b_sts(0);
    __syncthreads();

    constexpr int NS = HH / KSTAGE;   // 64 stages
    #pragma unroll 1
    for (int s = 0; s < NS; ++s) {
        const int cur = s & 1;
        if (s + 1 < NS) { a_ldg(g, Asrc, prow, pcol, s + 1); b_ldg(s + 1); }
        mma_stage_ldsm(smaddr + (cur * 2 + 0) * TILE_B,
                       smaddr + (cur * 2 + 1) * TILE_B,
                       smaddr + (4 + cur * 2 + 0) * TILE_B,
                       smaddr + (4 + cur * 2 + 1) * TILE_B,
                       wrow, wcol, lane, d);
        // same argument as the scan: previous end-of-iteration barrier already
        // ordered all warps past mma on buffer cur^1 -> safe to overwrite.
        if (s + 1 < NS) { a_sts(sm, cur ^ 1, g, prow, pcw); b_sts(cur ^ 1); }
        __syncthreads();
    }

    // epilogue: + bias, store
    #pragma unroll
    for (int m = 0; m < 2; ++m)
        #pragma unroll
        for (int n = 0; n < 8; ++n) {
            const int r0 = wrow + m * 16 + (lane >> 2);
            const int c0 = nbase + wcol + n * 8 + (lane & 3) * 2;
            const float2 bv = *(const float2*)(bo + c0);
            *(float2*)(out + (mbase + r0) * OO + c0) =
                make_float2(d[m][n][0] + bv.x, d[m][n][1] + bv.y);
            *(float2*)(out + (mbase + r0 + 8) * OO + c0) =
                make_float2(d[m][n][2] + bv.x, d[m][n][3] + bv.y);
        }
}

// ============================================================================
// Phase-1 fp32 FFMA2 GEMM (exact; verified R6 code)
// ============================================================================
typedef unsigned long long ull;
__device__ __forceinline__ void ffma2(ull& d, ull a, ull b) {
    asm("fma.rn.f32x2 %0, %1, %2, %3;" : "=l"(d) : "l"(a), "l"(b), "l"(d));
}
__device__ __forceinline__ void unpack2(float& lo, float& hi, ull v) {
    asm("mov.b64 {%0,%1}, %2;" : "=f"(lo), "=f"(hi) : "l"(v));
}
__device__ __forceinline__ ull dup2(float v) {
    ull r; asm("mov.b64 %0, {%1,%1};" : "=l"(r) : "f"(v)); return r;
}
constexpr int KB = 16;
struct SmemT {
    float As[2][KB][132];
    float Bs[2][KB][140];
};
__device__ __forceinline__ int skew(int n) { return n + ((n >> 5) << 2); }

__device__ __forceinline__ void gemm_tile(SmemT& s,
    const float* __restrict__ Ag, int lda,
    const float* __restrict__ Bg, int ldb,
    int nk, ull (&acc)[4][8])
{
    const int tid = threadIdx.x;
    const int am  = tid >> 2;
    const int ak  = (tid & 3) * 4;
    const int tm  = (tid >> 4) * 8;
    const int tn  = (tid & 15) * 8;
    const int ptn = skew(tn);
    const int pb0 = skew(am);
    const int pb1 = skew(am + 64);

    const float* Arow0 = Ag + (size_t)am        * lda + ak;
    const float* Arow1 = Ag + (size_t)(am + 64) * lda + ak;
    const float* Brow0 = Bg + (size_t)am        * ldb + ak;
    const float* Brow1 = Bg + (size_t)(am + 64) * ldb + ak;

    float4 ra0, ra1, rb0, rb1;
    auto ldg = [&](int kt) {
        const int kk = kt * KB;
        ra0 = *(const float4*)(Arow0 + kk);
        ra1 = *(const float4*)(Arow1 + kk);
        rb0 = *(const float4*)(Brow0 + kk);
        rb1 = *(const float4*)(Brow1 + kk);
    };
    auto sts = [&](int buf) {
        s.As[buf][ak + 0][am]      = ra0.x; s.As[buf][ak + 1][am]      = ra0.y;
        s.As[buf][ak + 2][am]      = ra0.z; s.As[buf][ak + 3][am]      = ra0.w;
        s.As[buf][ak + 0][am + 64] = ra1.x; s.As[buf][ak + 1][am + 64] = ra1.y;
        s.As[buf][ak + 2][am + 64] = ra1.z; s.As[buf][ak + 3][am + 64] = ra1.w;
        s.Bs[buf][ak + 0][pb0] = rb0.x; s.Bs[buf][ak + 1][pb0] = rb0.y;
        s.Bs[buf][ak + 2][pb0] = rb0.z; s.Bs[buf][ak + 3][pb0] = rb0.w;
        s.Bs[buf][ak + 0][pb1] = rb1.x; s.Bs[buf][ak + 1][pb1] = rb1.y;
        s.Bs[buf][ak + 2][pb1] = rb1.z; s.Bs[buf][ak + 3][pb1] = rb1.w;
    };

    ldg(0); sts(0);
    __syncthreads();
    for (int kt = 0; kt < nk; ++kt) {
        const int cur = kt & 1;
        if (kt + 1 < nk) ldg(kt + 1);
        #pragma unroll
        for (int k = 0; k < KB; ++k) {
            ulonglong2 a01 = *(const ulonglong2*)&s.As[cur][k][tm];
            ulonglong2 a23 = *(const ulonglong2*)&s.As[cur][k][tm + 4];
            float4 b0 = *(const float4*)&s.Bs[cur][k][ptn];
            float4 b1 = *(const float4*)&s.Bs[cur][k][ptn + 4];
            ull d0 = dup2(b0.x), d1 = dup2(b0.y), d2 = dup2(b0.z), d3 = dup2(b0.w);
            ull d4 = dup2(b1.x), d5 = dup2(b1.y), d6 = dup2(b1.z), d7 = dup2(b1.w);
            ffma2(acc[0][0], a01.x, d0); ffma2(acc[0][1], a01.x, d1);
            ffma2(acc[0][2], a01.x, d2); ffma2(acc[0][3], a01.x, d3);
            ffma2(acc[0][4], a01.x, d4); ffma2(acc[0][5], a01.x, d5);
            ffma2(acc[0][6], a01.x, d6); ffma2(acc[0][7], a01.x, d7);
            ffma2(acc[1][0], a01.y, d0); ffma2(acc[1][1], a01.y, d1);
            ffma2(acc[1][2], a01.y, d2); ffma2(acc[1][3], a01.y, d3);
            ffma2(acc[1][4], a01.y, d4); ffma2(acc[1][5], a01.y, d5);
            ffma2(acc[1][6], a01.y, d6); ffma2(acc[1][7], a01.y, d7);
            ffma2(acc[2][0], a23.x, d0); ffma2(acc[2][1], a23.x, d1);
            ffma2(acc[2][2], a23.x, d2); ffma2(acc[2][3], a23.x, d3);
            ffma2(acc[2][4], a23.x, d4); ffma2(acc[2][5], a23.x, d5);
            ffma2(acc[2][6], a23.x, d6); ffma2(acc[2][7], a23.x, d7);
            ffma2(acc[3][0], a23.y, d0); ffma2(acc[3][1], a23.y, d1);
            ffma2(acc[3][2], a23.y, d2); ffma2(acc[3][3], a23.y, d3);
            ffma2(acc[3][4], a23.y, d4); ffma2(acc[3][5], a23.y, d5);
            ffma2(acc[3][6], a23.y, d6); ffma2(acc[3][7], a23.y, d7);
        }
        if (kt + 1 < nk) sts(cur ^ 1);
        __syncthreads();
    }
}

__global__ void __launch_bounds__(NTH, 1)
gemm128(const float* __restrict__ A, int lda,
        const float* __restrict__ B, int ldb,
        float* __restrict__ C, int ldc,
        const float* __restrict__ bias, int K)
{
    __shared__ SmemT s;
    const int tid   = threadIdx.x;
    const int nbase = blockIdx.x * 128;
    const int mbase = blockIdx.y * 128;

    ull acc[4][8];
    #pragma unroll
    for (int p = 0; p < 4; ++p)
        #pragma unroll
        for (int n = 0; n < 8; ++n) acc[p][n] = 0ull;

    gemm_tile(s, A + (size_t)mbase * lda, lda, B + (size_t)nbase * ldb, ldb, K / KB, acc);

    const int tm = (tid >> 4) * 8;
    const int tn = (tid & 15) * 8;
    float bv[8];
    #pragma unroll
    for (int n = 0; n < 8; ++n) bv[n] = bias[nbase + tn + n];

    #pragma unroll
    for (int p = 0; p < 4; ++p) {
        float lo[8], hi[8];
        #pragma unroll
        for (int n = 0; n < 8; ++n) {
            unpack2(lo[n], hi[n], acc[p][n]);
            lo[n] += bv[n]; hi[n] += bv[n];
        }
        const int r0 = mbase + tm + 2 * p;
        float* c0 = C + (size_t)r0 * ldc + nbase + tn;
        float* c1 = c0 + ldc;
        *(float4*)(c0)     = make_float4(lo[0], lo[1], lo[2], lo[3]);
        *(float4*)(c0 + 4) = make_float4(lo[4], lo[5], lo[6], lo[7]);
        *(float4*)(c1)     = make_float4(hi[0], hi[1], hi[2], hi[3]);
        *(float4*)(c1 + 4) = make_float4(hi[4], hi[5], hi[6], hi[7]);
    }
}

__global__ void reset_ctr_kernel()
{
    const int i = blockIdx.x * blockDim.x + threadIdx.x;
    if (i < TT * NTILES) ((int*)g_ctr_tile)[i] = 0;
    if (i < TT) g_ctr_step[i] = 0;
}

__global__ void copy_h_kernel(float* __restrict__ dst)
{
    const int idx = blockIdx.x * blockDim.x + threadIdx.x;
    dst[idx] = g_hall[(size_t)(TT - 1) * BH + idx];
}

extern "C" void kernel_launch(void* const* d_in, const int* in_sizes, int n_in,
                              void* d_out, int out_size)
{
    (void)in_sizes; (void)n_in;
    const int*   x   = (const int*)  d_in[0];
    const float* emb = (const float*)d_in[1];
    const float* Wi  = (const float*)d_in[2];
    const float* bi  = (const float*)d_in[3];
    const float* Wh  = (const float*)d_in[4];
    const float* bh  = (const float*)d_in[5];
    const float* Wo  = (const float*)d_in[6];
    const float* bo  = (const float*)d_in[7];
    float* out = (float*)d_out;

    float* g_P_ptr = nullptr;
    cudaGetSymbolAddress((void**)&g_P_ptr, g_P);

    cudaFuncSetAttribute(scan_mma,     cudaFuncAttributeMaxDynamicSharedMemorySize, SMEM_SCAN);
    cudaFuncSetAttribute(gemm_out_mma, cudaFuncAttributeMaxDynamicSharedMemorySize, SMEM_P3);

    // Pre-split weights into bf16 hi/lo tiled layout (one-time per launch)
    presplit_wh<<<(128 * 8 * 128 * 16) / NTH, NTH>>>(Wh);
    presplit_wo<<<(4 * 64 * 128 * 16) / NTH, NTH>>>(Wo);

    // Phase 1: P = emb @ Wi^T + bi   [512 x 2048], K=512 (exact fp32)
    gemm128<<<dim3(HH / 128, VV / 128), NTH>>>(emb, VV, Wi, VV, g_P_ptr, HH, bi, VV);

    // Phase 2: persistent mma.sync scan (all 1024 steps, one launch)
    scan_mma<<<dim3(NTILES, KSPLIT), NTH, SMEM_SCAN>>>(x, bh);

    // Reset spin counters for the next replay
    reset_ctr_kernel<<<(TT * NTILES + NTH - 1) / NTH, NTH>>>();

    // Phase 3: out = h_all @ Wo^T + bo   [131072 x 512], K=2048
    gemm_out_mma<<<dim3(OO / 128, (TT * BB) / 128), NTH, SMEM_P3>>>(bo, out);

    // Second output: final hidden state h_{T-1}  [B, H]
    if ((long long)out_size >= (long long)(TBO + (size_t)BH))
        copy_h_kernel<<<BH / NTH, NTH>>>(out + TBO);
}

// round 11
// speedup vs baseline: 1.6763x; 1.0237x over previous
#include <cuda_runtime.h>
#include <cuda_bf16.h>
#include <math.h>
#include <cstdint>

// Problem dims
#define TT 1024
#define BB 128
#define VV 512
#define HH 2048
#define OO 512

constexpr int NTH    = 256;
constexpr int KSPLIT = 8;
constexpr int NTILES = HH / 128;     // 16
constexpr int KCH    = HH / KSPLIT;  // 256
constexpr int KSTAGE = 32;           // fp32 K-depth per stage

constexpr int    BH  = BB * HH;
constexpr size_t TBH = (size_t)TT * BH;
constexpr size_t TBO = (size_t)TT * BB * OO;

// Padded SMEM tile geometry: 128 rows x 16 data words (32 bf16) + 4 pad
constexpr int TW     = 20;                  // words per row
constexpr int TILE_W = 128 * TW;            // 2560 words per tile
constexpr int TILE_B = TILE_W * 4;          // 10240 bytes per tile

// Scan smem: A dbuf 4 tiles + Wh stationary 16 tiles = 20 tiles
constexpr int SMEM_SCAN = 20 * TILE_B;      // 204800 B
// Phase-3 smem: A dbuf 4 + B dbuf 4 = 8 tiles
constexpr int SMEM_P3   = 8 * TILE_B;       // 81920 B

// -------- device scratch --------
__device__ float g_P[VV * HH];
__device__ float g_hall[TBH];
__device__ float g_part[KSPLIT * (size_t)BH];
__device__ int   g_ctr_tile[TT][NTILES];    // split-K partial arrivals
__device__ int   g_ready[TT][NTILES];       // h-tile-ready counts (dataflow flags)
// Pre-split weights, tiled [slice][stage*2+hl][row(128)][word(16)]
__device__ uint4 g_whsplit4[(size_t)128 * 16 * 512];   // 16 MB
__device__ uint4 g_wosplit4[(size_t)4 * 128 * 512];    //  4 MB

// ============================================================================
// bf16x2 split + mma.sync + ldmatrix helpers
// ============================================================================
__device__ __forceinline__ void split2(float v0, float v1,
                                       uint32_t& whi, uint32_t& wlo) {
    __nv_bfloat16 h0 = __float2bfloat16_rn(v0);
    __nv_bfloat16 h1 = __float2bfloat16_rn(v1);
    __nv_bfloat16 l0 = __float2bfloat16_rn(v0 - __bfloat162float(h0));
    __nv_bfloat16 l1 = __float2bfloat16_rn(v1 - __bfloat162float(h1));
    whi = ((uint32_t)__bfloat16_as_ushort(h1) << 16) | __bfloat16_as_ushort(h0);
    wlo = ((uint32_t)__bfloat16_as_ushort(l1) << 16) | __bfloat16_as_ushort(l0);
}

__device__ __forceinline__ void mma_bf16(float* d, const uint32_t* a,
                                         const uint32_t* b) {
    asm volatile(
        "mma.sync.aligned.m16n8k16.row.col.f32.bf16.bf16.f32 "
        "{%0,%1,%2,%3}, {%4,%5,%6,%7}, {%8,%9}, {%0,%1,%2,%3};"
        : "+f"(d[0]), "+f"(d[1]), "+f"(d[2]), "+f"(d[3])
        : "r"(a[0]), "r"(a[1]), "r"(a[2]), "r"(a[3]), "r"(b[0]), "r"(b[1]));
}

__device__ __forceinline__ void ldsm4(uint32_t* r, uint32_t addr) {
    asm volatile("ldmatrix.sync.aligned.m8n8.x4.shared.b16 {%0,%1,%2,%3}, [%4];"
                 : "=r"(r[0]), "=r"(r[1]), "=r"(r[2]), "=r"(r[3]) : "r"(addr));
}

__device__ __forceinline__ uint32_t smem_u32(const void* p) {
    return (uint32_t)__cvta_generic_to_shared(p);
}

__device__ __forceinline__ void spin_ge(volatile int* p, int v) {
    while (*p < v) { }
}

// ============================================================================
// MMA stage via ldmatrix: warp tile 32 (M) x 64 (N), K=32, 3-product bf16x2.
// Per-accumulator product order (hh, hl, lh per k16) fixed -> stable numerics.
// ============================================================================
__device__ __forceinline__ void mma_stage_ldsm(
    uint32_t a_hi, uint32_t a_lo, uint32_t b_hi, uint32_t b_lo,
    int wrow, int wcol, int lane, float (&d)[2][8][4])
{
    const int arow = (lane & 7) + ((lane >> 3) & 1) * 8;
    const int acol = ((lane >> 4) & 1) * 4;
    const int brow = (lane & 7) + ((lane >> 4) & 1) * 8;
    const int bcol = ((lane >> 3) & 1) * 4;
    #pragma unroll
    for (int kk = 0; kk < 2; ++kk) {
        uint32_t ah[2][4], al[2][4];
        uint32_t bh[4][4], bl[4][4];
        #pragma unroll
        for (int m = 0; m < 2; ++m) {
            const uint32_t off =
                (uint32_t)(((wrow + m * 16 + arow) * TW + kk * 8 + acol) * 4);
            ldsm4(ah[m], a_hi + off);
            ldsm4(al[m], a_lo + off);
        }
        #pragma unroll
        for (int np = 0; np < 4; ++np) {
            const uint32_t off =
                (uint32_t)(((wcol + np * 16 + brow) * TW + kk * 8 + bcol) * 4);
            ldsm4(bh[np], b_hi + off);
            ldsm4(bl[np], b_lo + off);
        }
        #pragma unroll
        for (int np = 0; np < 4; ++np)
            #pragma unroll
            for (int h = 0; h < 2; ++h)
                #pragma unroll
                for (int m = 0; m < 2; ++m)
                    mma_bf16(d[m][2 * np + h], ah[m], &bh[np][2 * h]);
        #pragma unroll
        for (int np = 0; np < 4; ++np)
            #pragma unroll
            for (int h = 0; h < 2; ++h)
                #pragma unroll
                for (int m = 0; m < 2; ++m)
                    mma_bf16(d[m][2 * np + h], ah[m], &bl[np][2 * h]);
        #pragma unroll
        for (int np = 0; np < 4; ++np)
            #pragma unroll
            for (int h = 0; h < 2; ++h)
                #pragma unroll
                for (int m = 0; m < 2; ++m)
                    mma_bf16(d[m][2 * np + h], al[m], &bh[np][2 * h]);
    }
}

// A producer: thread covers row tid>>1, 16 floats at (tid&1)*16.
struct ARegs { float4 ra[4]; };

__device__ __forceinline__ void a_ldg(ARegs& g, const float* __restrict__ Asrc,
                                      int prow, int pcol, int s)
{
    const float* ap = Asrc + (size_t)prow * HH + pcol + s * KSTAGE;
    #pragma unroll
    for (int i = 0; i < 4; ++i) g.ra[i] = *(const float4*)(ap + 4 * i);
}

__device__ __forceinline__ void a_sts(uint32_t* sm, int buf, const ARegs& g,
                                      int prow, int pcw)
{
    uint32_t* hi = sm + (buf * 2 + 0) * TILE_W + prow * TW + pcw;
    uint32_t* lo = sm + (buf * 2 + 1) * TILE_W + prow * TW + pcw;
    #pragma unroll
    for (int i = 0; i < 4; ++i) {
        uint32_t h0, l0, h1, l1;
        split2(g.ra[i].x, g.ra[i].y, h0, l0);
        split2(g.ra[i].z, g.ra[i].w, h1, l1);
        *(uint2*)(hi + 2 * i) = make_uint2(h0, h1);
        *(uint2*)(lo + 2 * i) = make_uint2(l0, l1);
    }
}

// ============================================================================
// Weight pre-split kernels (run once per launch; tiny)
// ============================================================================
__global__ void presplit_wh(const float* __restrict__ Wh)
{
    const int idx = blockIdx.x * blockDim.x + threadIdx.x;  // < 128*8*128*16
    const int w     = idx & 15;
    const int row   = (idx >> 4) & 127;
    const int s     = (idx >> 11) & 7;
    const int slice = idx >> 14;          // j*8 + z
    const int j = slice >> 3, z = slice & 7;
    const int n = j * 128 + row;
    const int k = z * 256 + s * 32 + w * 2;
    uint32_t whi, wlo;
    split2(Wh[(size_t)n * HH + k], Wh[(size_t)n * HH + k + 1], whi, wlo);
    uint32_t* dst = (uint32_t*)g_whsplit4;
    const size_t tb = (((size_t)slice * 16 + s * 2) * 128 + row) * 16 + w;
    dst[tb] = whi;
    dst[tb + 128 * 16] = wlo;   // next tile (lo)
}

__global__ void presplit_wo(const float* __restrict__ Wo)
{
    const int idx = blockIdx.x * blockDim.x + threadIdx.x;  // < 4*64*128*16
    const int w   = idx & 15;
    const int row = (idx >> 4) & 127;
    const int s   = (idx >> 11) & 63;
    const int nj  = idx >> 17;
    const int n = nj * 128 + row;
    const int k = s * 32 + w * 2;
    uint32_t whi, wlo;
    split2(Wo[(size_t)n * HH + k], Wo[(size_t)n * HH + k + 1], whi, wlo);
    uint32_t* dst = (uint32_t*)g_wosplit4;
    const size_t tb = (((size_t)nj * 128 + s * 2) * 128 + row) * 16 + w;
    dst[tb] = whi;
    dst[tb + 128 * 16] = wlo;
}

// ============================================================================
// Persistent scan kernel: Wh stationary in SMEM, ldmatrix feeds, bf16x2 MMA.
// Synchronization is DATAFLOW: per-(t,tile) ready counters replace the global
// step barrier.  CTA (j,z) waits only on the 3 tiles it actually depends on:
//   - tiles 2z, 2z+1: producers of its h_{t-1} K-range
//   - tile j (own):   ready==8 <=> all group readers finished the step-(t-1)
//                     reduce, so this CTA's g_part plane is safe to overwrite.
// ============================================================================
__global__ void __launch_bounds__(NTH, 1)
scan_mma(const int* __restrict__ x,
         const float* __restrict__ bh)
{
    extern __shared__ uint32_t sm[];
    const uint32_t smaddr = smem_u32(sm);

    const int tid  = threadIdx.x;
    const int wid  = tid >> 5;
    const int lane = tid & 31;
    const int j    = blockIdx.x;
    const int z    = blockIdx.y;
    const int nbase = j * 128;
    const int k0    = z * KCH;
    const int p0    = 2 * z;
    const int p1    = 2 * z + 1;

    const int wrow = (wid & 3) * 32;
    const int wcol = (wid >> 2) * 64;
    const int prow = tid >> 1;
    const int pcol = (tid & 1) * 16;
    const int pcw  = (tid & 1) * 8;

    const int rrow  = tid >> 1;
    const int cbase = nbase + z * 16 + (tid & 1) * 8;

    // hoisted per-thread constants for the reduce
    const float4 bh0 = *(const float4*)(bh + cbase);
    const float4 bh1 = *(const float4*)(bh + cbase + 4);

    // ---- load this CTA's Wh slice (pre-split) into stationary SMEM tiles ----
    {
        const uint4* wsrc = g_whsplit4 + (size_t)(j * 8 + z) * 16 * 512;
        for (int r = tid; r < 16 * 128; r += NTH) {
            const int tile = r >> 7;
            const int row  = r & 127;
            uint32_t* dst = sm + (4 + tile) * TILE_W + row * TW;
            const uint4* s4 = wsrc + (size_t)r * 4;
            #pragma unroll
            for (int q = 0; q < 4; ++q)
                *(uint4*)(dst + 4 * q) = s4[q];
        }
    }

    // ---- t = 0: h_0 = tanh(P[x_0] + bh); arrive on ready[0][j] ----
    {
        const float* Pr = g_P + (size_t)x[rrow] * HH + cbase;
        float4 pp0 = *(const float4*)(Pr);
        float4 pp1 = *(const float4*)(Pr + 4);
        float* dst = g_hall + (size_t)rrow * HH + cbase;
        *(float4*)(dst)     = make_float4(tanhf(pp0.x + bh0.x), tanhf(pp0.y + bh0.y),
                                          tanhf(pp0.z + bh0.z), tanhf(pp0.w + bh0.w));
        *(float4*)(dst + 4) = make_float4(tanhf(pp1.x + bh1.x), tanhf(pp1.y + bh1.y),
                                          tanhf(pp1.z + bh1.z), tanhf(pp1.w + bh1.w));
        __threadfence();
        __syncthreads();
        if (tid == 0) atomicAdd(&g_ready[0][j], 1);
    }

    for (int t = 1; t < TT; ++t) {
        // ---- dataflow waits (3 concurrent spins in different warps) ----
        if      (tid == 0)  spin_ge(&g_ready[t - 1][p0], KSPLIT);
        else if (tid == 32) spin_ge(&g_ready[t - 1][p1], KSPLIT);
        else if (tid == 64) spin_ge(&g_ready[t - 1][j],  KSPLIT);
        __syncthreads();
        __threadfence();

        const float* Asrc = g_hall + (size_t)(t - 1) * BH + k0;

        // prefetch reduce-phase P gather (barrier-independent)
        const float* Pr = g_P + (size_t)x[(size_t)t * BB + rrow] * HH + cbase;
        const float4 pf0 = *(const float4*)(Pr);
        const float4 pf1 = *(const float4*)(Pr + 4);

        float d[2][8][4];
        #pragma unroll
        for (int m = 0; m < 2; ++m)
            #pragma unroll
            for (int n = 0; n < 8; ++n)
                #pragma unroll
                for (int q = 0; q < 4; ++q) d[m][n][q] = 0.0f;

        ARegs g;
        a_ldg(g, Asrc, prow, pcol, 0);
        a_sts(sm, 0, g, prow, pcw);
        __syncthreads();

        constexpr int NS = KCH / KSTAGE;   // 8 stages
        #pragma unroll 1
        for (int s = 0; s < NS; ++s) {
            const int cur = s & 1;
            if (s + 1 < NS) a_ldg(g, Asrc, prow, pcol, s + 1);
            mma_stage_ldsm(smaddr + (cur * 2 + 0) * TILE_B,
                           smaddr + (cur * 2 + 1) * TILE_B,
                           smaddr + (4 + s * 2 + 0) * TILE_B,
                           smaddr + (4 + s * 2 + 1) * TILE_B,
                           wrow, wcol, lane, d);
            if (s + 1 < NS) a_sts(sm, cur ^ 1, g, prow, pcw);
            __syncthreads();
        }

        // store split-K partial plane z (WAR-safe: own-tile ready wait above)
        {
            float* dst = g_part + (size_t)z * BH;
            #pragma unroll
            for (int m = 0; m < 2; ++m)
                #pragma unroll
                for (int n = 0; n < 8; ++n) {
                    const int r0 = wrow + m * 16 + (lane >> 2);
                    const int c0 = nbase + wcol + n * 8 + (lane & 3) * 2;
                    *(float2*)(dst + (size_t)r0 * HH + c0) =
                        make_float2(d[m][n][0], d[m][n][1]);
                    *(float2*)(dst + (size_t)(r0 + 8) * HH + c0) =
                        make_float2(d[m][n][2], d[m][n][3]);
                }
        }
        __threadfence();
        __syncthreads();

        // per-N-tile barrier: all 8 split-K planes of tile j present
        if (tid == 0) {
            atomicAdd(&g_ctr_tile[t][j], 1);
            spin_ge(&g_ctr_tile[t][j], KSPLIT);
            __threadfence();
        }
        __syncthreads();

        // distributed reduce + tanh over this CTA's 128x16 slice
        {
            float4 v0 = make_float4(pf0.x + bh0.x, pf0.y + bh0.y,
                                    pf0.z + bh0.z, pf0.w + bh0.w);
            float4 v1 = make_float4(pf1.x + bh1.x, pf1.y + bh1.y,
                                    pf1.z + bh1.z, pf1.w + bh1.w);
            const size_t off = (size_t)rrow * HH + cbase;
            #pragma unroll
            for (int z2 = 0; z2 < KSPLIT; ++z2) {
                float4 u0 = __ldcg((const float4*)(g_part + (size_t)z2 * BH + off));
                float4 u1 = __ldcg((const float4*)(g_part + (size_t)z2 * BH + off + 4));
                v0.x += u0.x; v0.y += u0.y; v0.z += u0.z; v0.w += u0.w;
                v1.x += u1.x; v1.y += u1.y; v1.z += u1.z; v1.w += u1.w;
            }
            float* dst = g_hall + (size_t)t * BH + off;
            *(float4*)(dst)     = make_float4(tanhf(v0.x), tanhf(v0.y),
                                              tanhf(v0.z), tanhf(v0.w));
            *(float4*)(dst + 4) = make_float4(tanhf(v1.x), tanhf(v1.y),
                                              tanhf(v1.z), tanhf(v1.w));
        }
        __threadfence();
        __syncthreads();

        // signal: this CTA's slice of h-tile j at step t is visible
        if (tid == 0) atomicAdd(&g_ready[t][j], 1);
    }
}

// ============================================================================
// Phase-3 GEMM: out = h_all @ Wo^T + bo.  A converted in-flight; B copied
// from pre-split tiles.  grid (4 N-tiles, 1024 M-tiles), K=2048 -> 64 stages.
// ============================================================================
__global__ void __launch_bounds__(NTH, 1)
gemm_out_mma(const float* __restrict__ bo,
             float* __restrict__ out)
{
    extern __shared__ uint32_t sm[];
    const uint32_t smaddr = smem_u32(sm);

    const int tid  = threadIdx.x;
    const int wid  = tid >> 5;
    const int lane = tid & 31;
    const int nj   = blockIdx.x;
    const int nbase = nj * 128;
    const size_t mbase = (size_t)blockIdx.y * 128;

    const int wrow = (wid & 3) * 32;
    const int wcol = (wid >> 2) * 64;
    const int prow = tid >> 1;
    const int pcol = (tid & 1) * 16;
    const int pcw  = (tid & 1) * 8;
    const int q0   = (tid & 1) * 2;

    const float* Asrc = g_hall + mbase * HH;
    const uint4* bsrc = g_wosplit4 + (size_t)nj * 128 * 512;

    float d[2][8][4];
    #pragma unroll
    for (int m = 0; m < 2; ++m)
        #pragma unroll
        for (int n = 0; n < 8; ++n)
            #pragma unroll
            for (int q = 0; q < 4; ++q) d[m][n][q] = 0.0f;

    ARegs g;
    uint4 bw[4];
    auto b_ldg = [&](int s) {
        const uint4* p = bsrc + (size_t)(s * 2) * 512 + (size_t)prow * 4 + q0;
        bw[0] = p[0];  bw[1] = p[1];          // hi tile, 2 uint4
        bw[2] = p[512]; bw[3] = p[513];       // lo tile
    };
    auto b_sts = [&](int buf) {
        uint32_t* hi = sm + (4 + buf * 2 + 0) * TILE_W + prow * TW + q0 * 4;
        uint32_t* lo = sm + (4 + buf * 2 + 1) * TILE_W + prow * TW + q0 * 4;
        *(uint4*)(hi)     = bw[0];
        *(uint4*)(hi + 4) = bw[1];
        *(uint4*)(lo)     = bw[2];
        *(uint4*)(lo + 4) = bw[3];
    };

    a_ldg(g, Asrc, prow, pcol, 0);
    b_ldg(0);
    a_sts(sm, 0, g, prow, pcw);
    b_sts(0);
    __syncthreads();

    constexpr int NS = HH / KSTAGE;   // 64 stages
    #pragma unroll 1
    for (int s = 0; s < NS; ++s) {
        const int cur = s & 1;
        if (s + 1 < NS) { a_ldg(g, Asrc, prow, pcol, s + 1); b_ldg(s + 1); }
        mma_stage_ldsm(smaddr + (cur * 2 + 0) * TILE_B,
                       smaddr + (cur * 2 + 1) * TILE_B,
                       smaddr + (4 + cur * 2 + 0) * TILE_B,
                       smaddr + (4 + cur * 2 + 1) * TILE_B,
                       wrow, wcol, lane, d);
        if (s + 1 < NS) { a_sts(sm, cur ^ 1, g, prow, pcw); b_sts(cur ^ 1); }
        __syncthreads();
    }

    // epilogue: + bias, store
    #pragma unroll
    for (int m = 0; m < 2; ++m)
        #pragma unroll
        for (int n = 0; n < 8; ++n) {
            const int r0 = wrow + m * 16 + (lane >> 2);
            const int c0 = nbase + wcol + n * 8 + (lane & 3) * 2;
            const float2 bv = *(const float2*)(bo + c0);
            *(float2*)(out + (mbase + r0) * OO + c0) =
                make_float2(d[m][n][0] + bv.x, d[m][n][1] + bv.y);
            *(float2*)(out + (mbase + r0 + 8) * OO + c0) =
                make_float2(d[m][n][2] + bv.x, d[m][n][3] + bv.y);
        }
}

// ============================================================================
// Phase-1 fp32 FFMA2 GEMM (exact; verified R6 code)
// ============================================================================
typedef unsigned long long ull;
__device__ __forceinline__ void ffma2(ull& d, ull a, ull b) {
    asm("fma.rn.f32x2 %0, %1, %2, %3;" : "=l"(d) : "l"(a), "l"(b), "l"(d));
}
__device__ __forceinline__ void unpack2(float& lo, float& hi, ull v) {
    asm("mov.b64 {%0,%1}, %2;" : "=f"(lo), "=f"(hi) : "l"(v));
}
__device__ __forceinline__ ull dup2(float v) {
    ull r; asm("mov.b64 %0, {%1,%1};" : "=l"(r) : "f"(v)); return r;
}
constexpr int KB = 16;
struct SmemT {
    float As[2][KB][132];
    float Bs[2][KB][140];
};
__device__ __forceinline__ int skew(int n) { return n + ((n >> 5) << 2); }

__device__ __forceinline__ void gemm_tile(SmemT& s,
    const float* __restrict__ Ag, int lda,
    const float* __restrict__ Bg, int ldb,
    int nk, ull (&acc)[4][8])
{
    const int tid = threadIdx.x;
    const int am  = tid >> 2;
    const int ak  = (tid & 3) * 4;
    const int tm  = (tid >> 4) * 8;
    const int tn  = (tid & 15) * 8;
    const int ptn = skew(tn);
    const int pb0 = skew(am);
    const int pb1 = skew(am + 64);

    const float* Arow0 = Ag + (size_t)am        * lda + ak;
    const float* Arow1 = Ag + (size_t)(am + 64) * lda + ak;
    const float* Brow0 = Bg + (size_t)am        * ldb + ak;
    const float* Brow1 = Bg + (size_t)(am + 64) * ldb + ak;

    float4 ra0, ra1, rb0, rb1;
    auto ldg = [&](int kt) {
        const int kk = kt * KB;
        ra0 = *(const float4*)(Arow0 + kk);
        ra1 = *(const float4*)(Arow1 + kk);
        rb0 = *(const float4*)(Brow0 + kk);
        rb1 = *(const float4*)(Brow1 + kk);
    };
    auto sts = [&](int buf) {
        s.As[buf][ak + 0][am]      = ra0.x; s.As[buf][ak + 1][am]      = ra0.y;
        s.As[buf][ak + 2][am]      = ra0.z; s.As[buf][ak + 3][am]      = ra0.w;
        s.As[buf][ak + 0][am + 64] = ra1.x; s.As[buf][ak + 1][am + 64] = ra1.y;
        s.As[buf][ak + 2][am + 64] = ra1.z; s.As[buf][ak + 3][am + 64] = ra1.w;
        s.Bs[buf][ak + 0][pb0] = rb0.x; s.Bs[buf][ak + 1][pb0] = rb0.y;
        s.Bs[buf][ak + 2][pb0] = rb0.z; s.Bs[buf][ak + 3][pb0] = rb0.w;
        s.Bs[buf][ak + 0][pb1] = rb1.x; s.Bs[buf][ak + 1][pb1] = rb1.y;
        s.Bs[buf][ak + 2][pb1] = rb1.z; s.Bs[buf][ak + 3][pb1] = rb1.w;
    };

    ldg(0); sts(0);
    __syncthreads();
    for (int kt = 0; kt < nk; ++kt) {
        const int cur = kt & 1;
        if (kt + 1 < nk) ldg(kt + 1);
        #pragma unroll
        for (int k = 0; k < KB; ++k) {
            ulonglong2 a01 = *(const ulonglong2*)&s.As[cur][k][tm];
            ulonglong2 a23 = *(const ulonglong2*)&s.As[cur][k][tm + 4];
            float4 b0 = *(const float4*)&s.Bs[cur][k][ptn];
            float4 b1 = *(const float4*)&s.Bs[cur][k][ptn + 4];
            ull d0 = dup2(b0.x), d1 = dup2(b0.y), d2 = dup2(b0.z), d3 = dup2(b0.w);
            ull d4 = dup2(b1.x), d5 = dup2(b1.y), d6 = dup2(b1.z), d7 = dup2(b1.w);
            ffma2(acc[0][0], a01.x, d0); ffma2(acc[0][1], a01.x, d1);
            ffma2(acc[0][2], a01.x, d2); ffma2(acc[0][3], a01.x, d3);
            ffma2(acc[0][4], a01.x, d4); ffma2(acc[0][5], a01.x, d5);
            ffma2(acc[0][6], a01.x, d6); ffma2(acc[0][7], a01.x, d7);
            ffma2(acc[1][0], a01.y, d0); ffma2(acc[1][1], a01.y, d1);
            ffma2(acc[1][2], a01.y, d2); ffma2(acc[1][3], a01.y, d3);
            ffma2(acc[1][4], a01.y, d4); ffma2(acc[1][5], a01.y, d5);
            ffma2(acc[1][6], a01.y, d6); ffma2(acc[1][7], a01.y, d7);
            ffma2(acc[2][0], a23.x, d0); ffma2(acc[2][1], a23.x, d1);
            ffma2(acc[2][2], a23.x, d2); ffma2(acc[2][3], a23.x, d3);
            ffma2(acc[2][4], a23.x, d4); ffma2(acc[2][5], a23.x, d5);
            ffma2(acc[2][6], a23.x, d6); ffma2(acc[2][7], a23.x, d7);
            ffma2(acc[3][0], a23.y, d0); ffma2(acc[3][1], a23.y, d1);
            ffma2(acc[3][2], a23.y, d2); ffma2(acc[3][3], a23.y, d3);
            ffma2(acc[3][4], a23.y, d4); ffma2(acc[3][5], a23.y, d5);
            ffma2(acc[3][6], a23.y, d6); ffma2(acc[3][7], a23.y, d7);
        }
        if (kt + 1 < nk) sts(cur ^ 1);
        __syncthreads();
    }
}

__global__ void __launch_bounds__(NTH, 1)
gemm128(const float* __restrict__ A, int lda,
        const float* __restrict__ B, int ldb,
        float* __restrict__ C, int ldc,
        const float* __restrict__ bias, int K)
{
    __shared__ SmemT s;
    const int tid   = threadIdx.x;
    const int nbase = blockIdx.x * 128;
    const int mbase = blockIdx.y * 128;

    ull acc[4][8];
    #pragma unroll
    for (int p = 0; p < 4; ++p)
        #pragma unroll
        for (int n = 0; n < 8; ++n) acc[p][n] = 0ull;

    gemm_tile(s, A + (size_t)mbase * lda, lda, B + (size_t)nbase * ldb, ldb, K / KB, acc);

    const int tm = (tid >> 4) * 8;
    const int tn = (tid & 15) * 8;
    float bv[8];
    #pragma unroll
    for (int n = 0; n < 8; ++n) bv[n] = bias[nbase + tn + n];

    #pragma unroll
    for (int p = 0; p < 4; ++p) {
        float lo[8], hi[8];
        #pragma unroll
        for (int n = 0; n < 8; ++n) {
            unpack2(lo[n], hi[n], acc[p][n]);
            lo[n] += bv[n]; hi[n] += bv[n];
        }
        const int r0 = mbase + tm + 2 * p;
        float* c0 = C + (size_t)r0 * ldc + nbase + tn;
        float* c1 = c0 + ldc;
        *(float4*)(c0)     = make_float4(lo[0], lo[1], lo[2], lo[3]);
        *(float4*)(c0 + 4) = make_float4(lo[4], lo[5], lo[6], lo[7]);
        *(float4*)(c1)     = make_float4(hi[0], hi[1], hi[2], hi[3]);
        *(float4*)(c1 + 4) = make_float4(hi[4], hi[5], hi[6], hi[7]);
    }
}

__global__ void reset_ctr_kernel()
{
    const int i = blockIdx.x * blockDim.x + threadIdx.x;
    if (i < TT * NTILES) {
        ((int*)g_ctr_tile)[i] = 0;
        ((int*)g_ready)[i] = 0;
    }
}

__global__ void copy_h_kernel(float* __restrict__ dst)
{
    const int idx = blockIdx.x * blockDim.x + threadIdx.x;
    dst[idx] = g_hall[(size_t)(TT - 1) * BH + idx];
}

extern "C" void kernel_launch(void* const* d_in, const int* in_sizes, int n_in,
                              void* d_out, int out_size)
{
    (void)in_sizes; (void)n_in;
    const int*   x   = (const int*)  d_in[0];
    const float* emb = (const float*)d_in[1];
    const float* Wi  = (const float*)d_in[2];
    const float* bi  = (const float*)d_in[3];
    const float* Wh  = (const float*)d_in[4];
    const float* bh  = (const float*)d_in[5];
    const float* Wo  = (const float*)d_in[6];
    const float* bo  = (const float*)d_in[7];
    float* out = (float*)d_out;

    float* g_P_ptr = nullptr;
    cudaGetSymbolAddress((void**)&g_P_ptr, g_P);

    cudaFuncSetAttribute(scan_mma,     cudaFuncAttributeMaxDynamicSharedMemorySize, SMEM_SCAN);
    cudaFuncSetAttribute(gemm_out_mma, cudaFuncAttributeMaxDynamicSharedMemorySize, SMEM_P3);

    // Pre-split weights into bf16 hi/lo tiled layout (one-time per launch)
    presplit_wh<<<(128 * 8 * 128 * 16) / NTH, NTH>>>(Wh);
    presplit_wo<<<(4 * 64 * 128 * 16) / NTH, NTH>>>(Wo);

    // Phase 1: P = emb @ Wi^T + bi   [512 x 2048], K=512 (exact fp32)
    gemm128<<<dim3(HH / 128, VV / 128), NTH>>>(emb, VV, Wi, VV, g_P_ptr, HH, bi, VV);

    // Phase 2: persistent mma.sync scan, dataflow-synchronized
    scan_mma<<<dim3(NTILES, KSPLIT), NTH, SMEM_SCAN>>>(x, bh);

    // Reset flags/counters for the next replay
    reset_ctr_kernel<<<(TT * NTILES + NTH - 1) / NTH, NTH>>>();

    // Phase 3: out = h_all @ Wo^T + bo   [131072 x 512], K=2048
    gemm_out_mma<<<dim3(OO / 128, (TT * BB) / 128), NTH, SMEM_P3>>>(bo, out);

    // Second output: final hidden state h_{T-1}  [B, H]
    if ((long long)out_size >= (long long)(TBO + (size_t)BH))
        copy_h_kernel<<<BH / NTH, NTH>>>(out + TBO);
}

// round 12
// speedup vs baseline: 1.7881x; 1.0667x over previous
#include <cuda_runtime.h>
#include <cuda_bf16.h>
#include <math.h>
#include <cstdint>

// Problem dims
#define TT 1024
#define BB 128
#define VV 512
#define HH 2048
#define OO 512

constexpr int NTH    = 256;
constexpr int KSPLIT = 8;
constexpr int NTILES = HH / 128;     // 16
constexpr int KCH    = HH / KSPLIT;  // 256
constexpr int KSTAGE = 32;           // fp32 K-depth per stage

constexpr int    BH  = BB * HH;
constexpr size_t TBH = (size_t)TT * BH;
constexpr size_t TBO = (size_t)TT * BB * OO;
constexpr size_t PART_STRIDE = (size_t)KSPLIT * BH;   // one parity buffer

// Padded SMEM tile geometry: 128 rows x 16 data words (32 bf16) + 4 pad
constexpr int TW     = 20;                  // words per row
constexpr int TILE_W = 128 * TW;            // 2560 words per tile
constexpr int TILE_B = TILE_W * 4;          // 10240 bytes per tile

constexpr int SMEM_SCAN = 20 * TILE_B;      // 204800 B
constexpr int SMEM_P3   = 8 * TILE_B;       // 81920 B

// -------- device scratch --------
__device__ float g_P[VV * HH];
__device__ float g_hall[TBH];
__device__ float g_part[2 * PART_STRIDE];   // parity double-buffered partials
__device__ int   g_ctr_tile[TT][NTILES];    // split-K partial arrivals
__device__ int   g_ready[TT][NTILES];       // h-tile-ready counts
// Pre-split weights, tiled [slice][stage*2+hl][row(128)][word(16)]
__device__ uint4 g_whsplit4[(size_t)128 * 16 * 512];   // 16 MB
__device__ uint4 g_wosplit4[(size_t)4 * 128 * 512];    //  4 MB

// ============================================================================
// sync + math helpers
// ============================================================================
__device__ __forceinline__ int ld_acquire(const int* p) {
    int v;
    asm volatile("ld.global.acquire.gpu.b32 %0, [%1];" : "=r"(v) : "l"(p) : "memory");
    return v;
}
__device__ __forceinline__ void red_release(int* p) {
    asm volatile("red.global.release.gpu.add.s32 [%0], 1;" :: "l"(p) : "memory");
}
__device__ __forceinline__ void spin_acq(const int* p, int v) {
    while (ld_acquire(p) < v) { }
}
// tanh(x) = 1 - 2/(exp2(2x*log2 e)+1); abs err ~2e-7 (MUFU-based)
__device__ __forceinline__ float fast_tanh(float x) {
    float e;
    asm("ex2.approx.f32 %0, %1;" : "=f"(e) : "f"(x * 2.8853900817779268f));
    float r;
    asm("rcp.approx.f32 %0, %1;" : "=f"(r) : "f"(e + 1.0f));
    return fmaf(-2.0f, r, 1.0f);
}

__device__ __forceinline__ void split2(float v0, float v1,
                                       uint32_t& whi, uint32_t& wlo) {
    __nv_bfloat16 h0 = __float2bfloat16_rn(v0);
    __nv_bfloat16 h1 = __float2bfloat16_rn(v1);
    __nv_bfloat16 l0 = __float2bfloat16_rn(v0 - __bfloat162float(h0));
    __nv_bfloat16 l1 = __float2bfloat16_rn(v1 - __bfloat162float(h1));
    whi = ((uint32_t)__bfloat16_as_ushort(h1) << 16) | __bfloat16_as_ushort(h0);
    wlo = ((uint32_t)__bfloat16_as_ushort(l1) << 16) | __bfloat16_as_ushort(l0);
}

__device__ __forceinline__ void mma_bf16(float* d, const uint32_t* a,
                                         const uint32_t* b) {
    asm volatile(
        "mma.sync.aligned.m16n8k16.row.col.f32.bf16.bf16.f32 "
        "{%0,%1,%2,%3}, {%4,%5,%6,%7}, {%8,%9}, {%0,%1,%2,%3};"
        : "+f"(d[0]), "+f"(d[1]), "+f"(d[2]), "+f"(d[3])
        : "r"(a[0]), "r"(a[1]), "r"(a[2]), "r"(a[3]), "r"(b[0]), "r"(b[1]));
}

__device__ __forceinline__ void ldsm4(uint32_t* r, uint32_t addr) {
    asm volatile("ldmatrix.sync.aligned.m8n8.x4.shared.b16 {%0,%1,%2,%3}, [%4];"
                 : "=r"(r[0]), "=r"(r[1]), "=r"(r[2]), "=r"(r[3]) : "r"(addr));
}

__device__ __forceinline__ uint32_t smem_u32(const void* p) {
    return (uint32_t)__cvta_generic_to_shared(p);
}

// ============================================================================
// MMA stage via ldmatrix: warp tile 32 (M) x 64 (N), K=32, 3-product bf16x2.
// Per-accumulator product order (hh, hl, lh per k16) fixed -> stable numerics.
// ============================================================================
__device__ __forceinline__ void mma_stage_ldsm(
    uint32_t a_hi, uint32_t a_lo, uint32_t b_hi, uint32_t b_lo,
    int wrow, int wcol, int lane, float (&d)[2][8][4])
{
    const int arow = (lane & 7) + ((lane >> 3) & 1) * 8;
    const int acol = ((lane >> 4) & 1) * 4;
    const int brow = (lane & 7) + ((lane >> 4) & 1) * 8;
    const int bcol = ((lane >> 3) & 1) * 4;
    #pragma unroll
    for (int kk = 0; kk < 2; ++kk) {
        uint32_t ah[2][4], al[2][4];
        uint32_t bh[4][4], bl[4][4];
        #pragma unroll
        for (int m = 0; m < 2; ++m) {
            const uint32_t off =
                (uint32_t)(((wrow + m * 16 + arow) * TW + kk * 8 + acol) * 4);
            ldsm4(ah[m], a_hi + off);
            ldsm4(al[m], a_lo + off);
        }
        #pragma unroll
        for (int np = 0; np < 4; ++np) {
            const uint32_t off =
                (uint32_t)(((wcol + np * 16 + brow) * TW + kk * 8 + bcol) * 4);
            ldsm4(bh[np], b_hi + off);
            ldsm4(bl[np], b_lo + off);
        }
        #pragma unroll
        for (int np = 0; np < 4; ++np)
            #pragma unroll
            for (int h = 0; h < 2; ++h)
                #pragma unroll
                for (int m = 0; m < 2; ++m)
                    mma_bf16(d[m][2 * np + h], ah[m], &bh[np][2 * h]);
        #pragma unroll
        for (int np = 0; np < 4; ++np)
            #pragma unroll
            for (int h = 0; h < 2; ++h)
                #pragma unroll
                for (int m = 0; m < 2; ++m)
                    mma_bf16(d[m][2 * np + h], ah[m], &bl[np][2 * h]);
        #pragma unroll
        for (int np = 0; np < 4; ++np)
            #pragma unroll
            for (int h = 0; h < 2; ++h)
                #pragma unroll
                for (int m = 0; m < 2; ++m)
                    mma_bf16(d[m][2 * np + h], al[m], &bh[np][2 * h]);
    }
}

// A producer: thread covers row tid>>1, 16 floats at (tid&1)*16.
struct ARegs { float4 ra[4]; };

__device__ __forceinline__ void a_ldg(ARegs& g, const float* __restrict__ Asrc,
                                      int prow, int pcol, int s)
{
    const float* ap = Asrc + (size_t)prow * HH + pcol + s * KSTAGE;
    #pragma unroll
    for (int i = 0; i < 4; ++i) g.ra[i] = *(const float4*)(ap + 4 * i);
}

__device__ __forceinline__ void a_sts(uint32_t* sm, int buf, const ARegs& g,
                                      int prow, int pcw)
{
    uint32_t* hi = sm + (buf * 2 + 0) * TILE_W + prow * TW + pcw;
    uint32_t* lo = sm + (buf * 2 + 1) * TILE_W + prow * TW + pcw;
    #pragma unroll
    for (int i = 0; i < 4; ++i) {
        uint32_t h0, l0, h1, l1;
        split2(g.ra[i].x, g.ra[i].y, h0, l0);
        split2(g.ra[i].z, g.ra[i].w, h1, l1);
        *(uint2*)(hi + 2 * i) = make_uint2(h0, h1);
        *(uint2*)(lo + 2 * i) = make_uint2(l0, l1);
    }
}

// ============================================================================
// Weight pre-split kernels (run once per launch; tiny)
// ============================================================================
__global__ void presplit_wh(const float* __restrict__ Wh)
{
    const int idx = blockIdx.x * blockDim.x + threadIdx.x;  // < 128*8*128*16
    const int w     = idx & 15;
    const int row   = (idx >> 4) & 127;
    const int s     = (idx >> 11) & 7;
    const int slice = idx >> 14;          // j*8 + z
    const int j = slice >> 3, z = slice & 7;
    const int n = j * 128 + row;
    const int k = z * 256 + s * 32 + w * 2;
    uint32_t whi, wlo;
    split2(Wh[(size_t)n * HH + k], Wh[(size_t)n * HH + k + 1], whi, wlo);
    uint32_t* dst = (uint32_t*)g_whsplit4;
    const size_t tb = (((size_t)slice * 16 + s * 2) * 128 + row) * 16 + w;
    dst[tb] = whi;
    dst[tb + 128 * 16] = wlo;   // next tile (lo)
}

__global__ void presplit_wo(const float* __restrict__ Wo)
{
    const int idx = blockIdx.x * blockDim.x + threadIdx.x;  // < 4*64*128*16
    const int w   = idx & 15;
    const int row = (idx >> 4) & 127;
    const int s   = (idx >> 11) & 63;
    const int nj  = idx >> 17;
    const int n = nj * 128 + row;
    const int k = s * 32 + w * 2;
    uint32_t whi, wlo;
    split2(Wo[(size_t)n * HH + k], Wo[(size_t)n * HH + k + 1], whi, wlo);
    uint32_t* dst = (uint32_t*)g_wosplit4;
    const size_t tb = (((size_t)nj * 128 + s * 2) * 128 + row) * 16 + w;
    dst[tb] = whi;
    dst[tb + 128 * 16] = wlo;
}

// ============================================================================
// Persistent scan kernel.  Dataflow sync with single-thread release/acquire:
//  - producers of h tiles 2z, 2z+1 at t-1 (ld.acquire spins)
//  - parity-buffered partials: WAR guard is g_ready[t-2][j] (near-free)
//  - NO all-thread membar: plain stores + bar.sync + one red.release.gpu
// ============================================================================
__global__ void __launch_bounds__(NTH, 1)
scan_mma(const int* __restrict__ x,
         const float* __restrict__ bh)
{
    extern __shared__ uint32_t sm[];
    const uint32_t smaddr = smem_u32(sm);

    const int tid  = threadIdx.x;
    const int wid  = tid >> 5;
    const int lane = tid & 31;
    const int j    = blockIdx.x;
    const int z    = blockIdx.y;
    const int nbase = j * 128;
    const int k0    = z * KCH;
    const int p0    = 2 * z;
    const int p1    = 2 * z + 1;

    const int wrow = (wid & 3) * 32;
    const int wcol = (wid >> 2) * 64;
    const int prow = tid >> 1;
    const int pcol = (tid & 1) * 16;
    const int pcw  = (tid & 1) * 8;

    const int rrow  = tid >> 1;
    const int cbase = nbase + z * 16 + (tid & 1) * 8;

    const float4 bh0 = *(const float4*)(bh + cbase);
    const float4 bh1 = *(const float4*)(bh + cbase + 4);

    // ---- load this CTA's Wh slice (pre-split) into stationary SMEM tiles ----
    {
        const uint4* wsrc = g_whsplit4 + (size_t)(j * 8 + z) * 16 * 512;
        for (int r = tid; r < 16 * 128; r += NTH) {
            const int tile = r >> 7;
            const int row  = r & 127;
            uint32_t* dst = sm + (4 + tile) * TILE_W + row * TW;
            const uint4* s4 = wsrc + (size_t)r * 4;
            #pragma unroll
            for (int q = 0; q < 4; ++q)
                *(uint4*)(dst + 4 * q) = s4[q];
        }
    }

    // ---- t = 0: h_0 = tanh(P[x_0] + bh); signal ready[0][j] ----
    {
        const float* Pr = g_P + (size_t)x[rrow] * HH + cbase;
        float4 pp0 = *(const float4*)(Pr);
        float4 pp1 = *(const float4*)(Pr + 4);
        float* dst = g_hall + (size_t)rrow * HH + cbase;
        *(float4*)(dst)     = make_float4(fast_tanh(pp0.x + bh0.x), fast_tanh(pp0.y + bh0.y),
                                          fast_tanh(pp0.z + bh0.z), fast_tanh(pp0.w + bh0.w));
        *(float4*)(dst + 4) = make_float4(fast_tanh(pp1.x + bh1.x), fast_tanh(pp1.y + bh1.y),
                                          fast_tanh(pp1.z + bh1.z), fast_tanh(pp1.w + bh1.w));
        __syncthreads();
        if (tid == 0) red_release(&g_ready[0][j]);
    }

    for (int t = 1; t < TT; ++t) {
        // ---- dataflow waits (acquire spins, separate warps) ----
        if      (tid == 0)  spin_acq(&g_ready[t - 1][p0], KSPLIT);
        else if (tid == 32) spin_acq(&g_ready[t - 1][p1], KSPLIT);
        else if (tid == 64 && t >= 2) spin_acq(&g_ready[t - 2][j], KSPLIT);
        __syncthreads();

        const float* Asrc = g_hall + (size_t)(t - 1) * BH + k0;
        float* part = g_part + (size_t)(t & 1) * PART_STRIDE + (size_t)z * BH;
        const float* pplane = g_part + (size_t)(t & 1) * PART_STRIDE;

        // prefetch reduce-phase P gather (barrier-independent)
        const float* Pr = g_P + (size_t)x[(size_t)t * BB + rrow] * HH + cbase;
        const float4 pf0 = *(const float4*)(Pr);
        const float4 pf1 = *(const float4*)(Pr + 4);

        float d[2][8][4];
        #pragma unroll
        for (int m = 0; m < 2; ++m)
            #pragma unroll
            for (int n = 0; n < 8; ++n)
                #pragma unroll
                for (int q = 0; q < 4; ++q) d[m][n][q] = 0.0f;

        ARegs g;
        a_ldg(g, Asrc, prow, pcol, 0);
        a_sts(sm, 0, g, prow, pcw);
        __syncthreads();

        constexpr int NS = KCH / KSTAGE;   // 8 stages
        #pragma unroll 1
        for (int s = 0; s < NS; ++s) {
            const int cur = s & 1;
            if (s + 1 < NS) a_ldg(g, Asrc, prow, pcol, s + 1);
            mma_stage_ldsm(smaddr + (cur * 2 + 0) * TILE_B,
                           smaddr + (cur * 2 + 1) * TILE_B,
                           smaddr + (4 + s * 2 + 0) * TILE_B,
                           smaddr + (4 + s * 2 + 1) * TILE_B,
                           wrow, wcol, lane, d);
            if (s + 1 < NS) a_sts(sm, cur ^ 1, g, prow, pcw);
            __syncthreads();
        }

        // store split-K partial plane (parity buffer; WAR-safe via t-2 wait)
        #pragma unroll
        for (int m = 0; m < 2; ++m)
            #pragma unroll
            for (int n = 0; n < 8; ++n) {
                const int r0 = wrow + m * 16 + (lane >> 2);
                const int c0 = nbase + wcol + n * 8 + (lane & 3) * 2;
                *(float2*)(part + (size_t)r0 * HH + c0) =
                    make_float2(d[m][n][0], d[m][n][1]);
                *(float2*)(part + (size_t)(r0 + 8) * HH + c0) =
                    make_float2(d[m][n][2], d[m][n][3]);
            }
        __syncthreads();

        // tile barrier: bar orders all CTA stores before tid0's release-red
        if (tid == 0) {
            red_release(&g_ctr_tile[t][j]);
            spin_acq(&g_ctr_tile[t][j], KSPLIT);
        }
        __syncthreads();

        // distributed reduce + tanh over this CTA's 128x16 slice
        {
            float4 v0 = make_float4(pf0.x + bh0.x, pf0.y + bh0.y,
                                    pf0.z + bh0.z, pf0.w + bh0.w);
            float4 v1 = make_float4(pf1.x + bh1.x, pf1.y + bh1.y,
                                    pf1.z + bh1.z, pf1.w + bh1.w);
            const size_t off = (size_t)rrow * HH + cbase;
            #pragma unroll
            for (int z2 = 0; z2 < KSPLIT; ++z2) {
                float4 u0 = __ldcg((const float4*)(pplane + (size_t)z2 * BH + off));
                float4 u1 = __ldcg((const float4*)(pplane + (size_t)z2 * BH + off + 4));
                v0.x += u0.x; v0.y += u0.y; v0.z += u0.z; v0.w += u0.w;
                v1.x += u1.x; v1.y += u1.y; v1.z += u1.z; v1.w += u1.w;
            }
            float* dst = g_hall + (size_t)t * BH + off;
            *(float4*)(dst)     = make_float4(fast_tanh(v0.x), fast_tanh(v0.y),
                                              fast_tanh(v0.z), fast_tanh(v0.w));
            *(float4*)(dst + 4) = make_float4(fast_tanh(v1.x), fast_tanh(v1.y),
                                              fast_tanh(v1.z), fast_tanh(v1.w));
        }
        __syncthreads();

        // signal: this CTA's slice of h-tile j at step t is visible
        if (tid == 0) red_release(&g_ready[t][j]);
    }
}

// ============================================================================
// Phase-3 GEMM: out = h_all @ Wo^T + bo.  A converted in-flight; B copied
// from pre-split tiles.  grid (4 N-tiles, 1024 M-tiles), K=2048 -> 64 stages.
// ============================================================================
__global__ void __launch_bounds__(NTH, 1)
gemm_out_mma(const float* __restrict__ bo,
             float* __restrict__ out)
{
    extern __shared__ uint32_t sm[];
    const uint32_t smaddr = smem_u32(sm);

    const int tid  = threadIdx.x;
    const int wid  = tid >> 5;
    const int lane = tid & 31;
    const int nj   = blockIdx.x;
    const int nbase = nj * 128;
    const size_t mbase = (size_t)blockIdx.y * 128;

    const int wrow = (wid & 3) * 32;
    const int wcol = (wid >> 2) * 64;
    const int prow = tid >> 1;
    const int pcol = (tid & 1) * 16;
    const int pcw  = (tid & 1) * 8;
    const int q0   = (tid & 1) * 2;

    const float* Asrc = g_hall + mbase * HH;
    const uint4* bsrc = g_wosplit4 + (size_t)nj * 128 * 512;

    float d[2][8][4];
    #pragma unroll
    for (int m = 0; m < 2; ++m)
        #pragma unroll
        for (int n = 0; n < 8; ++n)
            #pragma unroll
            for (int q = 0; q < 4; ++q) d[m][n][q] = 0.0f;

    ARegs g;
    uint4 bw[4];
    auto b_ldg = [&](int s) {
        const uint4* p = bsrc + (size_t)(s * 2) * 512 + (size_t)prow * 4 + q0;
        bw[0] = p[0];  bw[1] = p[1];          // hi tile, 2 uint4
        bw[2] = p[512]; bw[3] = p[513];       // lo tile
    };
    auto b_sts = [&](int buf) {
        uint32_t* hi = sm + (4 + buf * 2 + 0) * TILE_W + prow * TW + q0 * 4;
        uint32_t* lo = sm + (4 + buf * 2 + 1) * TILE_W + prow * TW + q0 * 4;
        *(uint4*)(hi)     = bw[0];
        *(uint4*)(hi + 4) = bw[1];
        *(uint4*)(lo)     = bw[2];
        *(uint4*)(lo + 4) = bw[3];
    };

    a_ldg(g, Asrc, prow, pcol, 0);
    b_ldg(0);
    a_sts(sm, 0, g, prow, pcw);
    b_sts(0);
    __syncthreads();

    constexpr int NS = HH / KSTAGE;   // 64 stages
    #pragma unroll 1
    for (int s = 0; s < NS; ++s) {
        const int cur = s & 1;
        if (s + 1 < NS) { a_ldg(g, Asrc, prow, pcol, s + 1); b_ldg(s + 1); }
        mma_stage_ldsm(smaddr + (cur * 2 + 0) * TILE_B,
                       smaddr + (cur * 2 + 1) * TILE_B,
                       smaddr + (4 + cur * 2 + 0) * TILE_B,
                       smaddr + (4 + cur * 2 + 1) * TILE_B,
                       wrow, wcol, lane, d);
        if (s + 1 < NS) { a_sts(sm, cur ^ 1, g, prow, pcw); b_sts(cur ^ 1); }
        __syncthreads();
    }

    // epilogue: + bias, store
    #pragma unroll
    for (int m = 0; m < 2; ++m)
        #pragma unroll
        for (int n = 0; n < 8; ++n) {
            const int r0 = wrow + m * 16 + (lane >> 2);
            const int c0 = nbase + wcol + n * 8 + (lane & 3) * 2;
            const float2 bv = *(const float2*)(bo + c0);
            *(float2*)(out + (mbase + r0) * OO + c0) =
                make_float2(d[m][n][0] + bv.x, d[m][n][1] + bv.y);
            *(float2*)(out + (mbase + r0 + 8) * OO + c0) =
                make_float2(d[m][n][2] + bv.x, d[m][n][3] + bv.y);
        }
}

// ============================================================================
// Phase-1 fp32 FFMA2 GEMM (exact; verified R6 code)
// ============================================================================
typedef unsigned long long ull;
__device__ __forceinline__ void ffma2(ull& d, ull a, ull b) {
    asm("fma.rn.f32x2 %0, %1, %2, %3;" : "=l"(d) : "l"(a), "l"(b), "l"(d));
}
__device__ __forceinline__ void unpack2(float& lo, float& hi, ull v) {
    asm("mov.b64 {%0,%1}, %2;" : "=f"(lo), "=f"(hi) : "l"(v));
}
__device__ __forceinline__ ull dup2(float v) {
    ull r; asm("mov.b64 %0, {%1,%1};" : "=l"(r) : "f"(v)); return r;
}
constexpr int KB = 16;
struct SmemT {
    float As[2][KB][132];
    float Bs[2][KB][140];
};
__device__ __forceinline__ int skew(int n) { return n + ((n >> 5) << 2); }

__device__ __forceinline__ void gemm_tile(SmemT& s,
    const float* __restrict__ Ag, int lda,
    const float* __restrict__ Bg, int ldb,
    int nk, ull (&acc)[4][8])
{
    const int tid = threadIdx.x;
    const int am  = tid >> 2;
    const int ak  = (tid & 3) * 4;
    const int tm  = (tid >> 4) * 8;
    const int tn  = (tid & 15) * 8;
    const int ptn = skew(tn);
    const int pb0 = skew(am);
    const int pb1 = skew(am + 64);

    const float* Arow0 = Ag + (size_t)am        * lda + ak;
    const float* Arow1 = Ag + (size_t)(am + 64) * lda + ak;
    const float* Brow0 = Bg + (size_t)am        * ldb + ak;
    const float* Brow1 = Bg + (size_t)(am + 64) * ldb + ak;

    float4 ra0, ra1, rb0, rb1;
    auto ldg = [&](int kt) {
        const int kk = kt * KB;
        ra0 = *(const float4*)(Arow0 + kk);
        ra1 = *(const float4*)(Arow1 + kk);
        rb0 = *(const float4*)(Brow0 + kk);
        rb1 = *(const float4*)(Brow1 + kk);
    };
    auto sts = [&](int buf) {
        s.As[buf][ak + 0][am]      = ra0.x; s.As[buf][ak + 1][am]      = ra0.y;
        s.As[buf][ak + 2][am]      = ra0.z; s.As[buf][ak + 3][am]      = ra0.w;
        s.As[buf][ak + 0][am + 64] = ra1.x; s.As[buf][ak + 1][am + 64] = ra1.y;
        s.As[buf][ak + 2][am + 64] = ra1.z; s.As[buf][ak + 3][am + 64] = ra1.w;
        s.Bs[buf][ak + 0][pb0] = rb0.x; s.Bs[buf][ak + 1][pb0] = rb0.y;
        s.Bs[buf][ak + 2][pb0] = rb0.z; s.Bs[buf][ak + 3][pb0] = rb0.w;
        s.Bs[buf][ak + 0][pb1] = rb1.x; s.Bs[buf][ak + 1][pb1] = rb1.y;
        s.Bs[buf][ak + 2][pb1] = rb1.z; s.Bs[buf][ak + 3][pb1] = rb1.w;
    };

    ldg(0); sts(0);
    __syncthreads();
    for (int kt = 0; kt < nk; ++kt) {
        const int cur = kt & 1;
        if (kt + 1 < nk) ldg(kt + 1);
        #pragma unroll
        for (int k = 0; k < KB; ++k) {
            ulonglong2 a01 = *(const ulonglong2*)&s.As[cur][k][tm];
            ulonglong2 a23 = *(const ulonglong2*)&s.As[cur][k][tm + 4];
            float4 b0 = *(const float4*)&s.Bs[cur][k][ptn];
            float4 b1 = *(const float4*)&s.Bs[cur][k][ptn + 4];
            ull d0 = dup2(b0.x), d1 = dup2(b0.y), d2 = dup2(b0.z), d3 = dup2(b0.w);
            ull d4 = dup2(b1.x), d5 = dup2(b1.y), d6 = dup2(b1.z), d7 = dup2(b1.w);
            ffma2(acc[0][0], a01.x, d0); ffma2(acc[0][1], a01.x, d1);
            ffma2(acc[0][2], a01.x, d2); ffma2(acc[0][3], a01.x, d3);
            ffma2(acc[0][4], a01.x, d4); ffma2(acc[0][5], a01.x, d5);
            ffma2(acc[0][6], a01.x, d6); ffma2(acc[0][7], a01.x, d7);
            ffma2(acc[1][0], a01.y, d0); ffma2(acc[1][1], a01.y, d1);
            ffma2(acc[1][2], a01.y, d2); ffma2(acc[1][3], a01.y, d3);
            ffma2(acc[1][4], a01.y, d4); ffma2(acc[1][5], a01.y, d5);
            ffma2(acc[1][6], a01.y, d6); ffma2(acc[1][7], a01.y, d7);
            ffma2(acc[2][0], a23.x, d0); ffma2(acc[2][1], a23.x, d1);
            ffma2(acc[2][2], a23.x, d2); ffma2(acc[2][3], a23.x, d3);
            ffma2(acc[2][4], a23.x, d4); ffma2(acc[2][5], a23.x, d5);
            ffma2(acc[2][6], a23.x, d6); ffma2(acc[2][7], a23.x, d7);
            ffma2(acc[3][0], a23.y, d0); ffma2(acc[3][1], a23.y, d1);
            ffma2(acc[3][2], a23.y, d2); ffma2(acc[3][3], a23.y, d3);
            ffma2(acc[3][4], a23.y, d4); ffma2(acc[3][5], a23.y, d5);
            ffma2(acc[3][6], a23.y, d6); ffma2(acc[3][7], a23.y, d7);
        }
        if (kt + 1 < nk) sts(cur ^ 1);
        __syncthreads();
    }
}

__global__ void __launch_bounds__(NTH, 1)
gemm128(const float* __restrict__ A, int lda,
        const float* __restrict__ B, int ldb,
        float* __restrict__ C, int ldc,
        const float* __restrict__ bias, int K)
{
    __shared__ SmemT s;
    const int tid   = threadIdx.x;
    const int nbase = blockIdx.x * 128;
    const int mbase = blockIdx.y * 128;

    ull acc[4][8];
    #pragma unroll
    for (int p = 0; p < 4; ++p)
        #pragma unroll
        for (int n = 0; n < 8; ++n) acc[p][n] = 0ull;

    gemm_tile(s, A + (size_t)mbase * lda, lda, B + (size_t)nbase * ldb, ldb, K / KB, acc);

    const int tm = (tid >> 4) * 8;
    const int tn = (tid & 15) * 8;
    float bv[8];
    #pragma unroll
    for (int n = 0; n < 8; ++n) bv[n] = bias[nbase + tn + n];

    #pragma unroll
    for (int p = 0; p < 4; ++p) {
        float lo[8], hi[8];
        #pragma unroll
        for (int n = 0; n < 8; ++n) {
            unpack2(lo[n], hi[n], acc[p][n]);
            lo[n] += bv[n]; hi[n] += bv[n];
        }
        const int r0 = mbase + tm + 2 * p;
        float* c0 = C + (size_t)r0 * ldc + nbase + tn;
        float* c1 = c0 + ldc;
        *(float4*)(c0)     = make_float4(lo[0], lo[1], lo[2], lo[3]);
        *(float4*)(c0 + 4) = make_float4(lo[4], lo[5], lo[6], lo[7]);
        *(float4*)(c1)     = make_float4(hi[0], hi[1], hi[2], hi[3]);
        *(float4*)(c1 + 4) = make_float4(hi[4], hi[5], hi[6], hi[7]);
    }
}

__global__ void reset_ctr_kernel()
{
    const int i = blockIdx.x * blockDim.x + threadIdx.x;
    if (i < TT * NTILES) {
        ((int*)g_ctr_tile)[i] = 0;
        ((int*)g_ready)[i] = 0;
    }
}

__global__ void copy_h_kernel(float* __restrict__ dst)
{
    const int idx = blockIdx.x * blockDim.x + threadIdx.x;
    dst[idx] = g_hall[(size_t)(TT - 1) * BH + idx];
}

extern "C" void kernel_launch(void* const* d_in, const int* in_sizes, int n_in,
                              void* d_out, int out_size)
{
    (void)in_sizes; (void)n_in;
    const int*   x   = (const int*)  d_in[0];
    const float* emb = (const float*)d_in[1];
    const float* Wi  = (const float*)d_in[2];
    const float* bi  = (const float*)d_in[3];
    const float* Wh  = (const float*)d_in[4];
    const float* bh  = (const float*)d_in[5];
    const float* Wo  = (const float*)d_in[6];
    const float* bo  = (const float*)d_in[7];
    float* out = (float*)d_out;

    float* g_P_ptr = nullptr;
    cudaGetSymbolAddress((void**)&g_P_ptr, g_P);

    cudaFuncSetAttribute(scan_mma,     cudaFuncAttributeMaxDynamicSharedMemorySize, SMEM_SCAN);
    cudaFuncSetAttribute(gemm_out_mma, cudaFuncAttributeMaxDynamicSharedMemorySize, SMEM_P3);

    // Pre-split weights into bf16 hi/lo tiled layout (one-time per launch)
    presplit_wh<<<(128 * 8 * 128 * 16) / NTH, NTH>>>(Wh);
    presplit_wo<<<(4 * 64 * 128 * 16) / NTH, NTH>>>(Wo);

    // Phase 1: P = emb @ Wi^T + bi   [512 x 2048], K=512 (exact fp32)
    gemm128<<<dim3(HH / 128, VV / 128), NTH>>>(emb, VV, Wi, VV, g_P_ptr, HH, bi, VV);

    // Phase 2: persistent mma.sync scan, dataflow-synchronized
    scan_mma<<<dim3(NTILES, KSPLIT), NTH, SMEM_SCAN>>>(x, bh);

    // Reset flags/counters for the next replay
    reset_ctr_kernel<<<(TT * NTILES + NTH - 1) / NTH, NTH>>>();

    // Phase 3: out = h_all @ Wo^T + bo   [131072 x 512], K=2048
    gemm_out_mma<<<dim3(OO / 128, (TT * BB) / 128), NTH, SMEM_P3>>>(bo, out);

    // Second output: final hidden state h_{T-1}  [B, H]
    if ((long long)out_size >= (long long)(TBO + (size_t)BH))
        copy_h_kernel<<<BH / NTH, NTH>>>(out + TBO);
}